// round 7
// baseline (speedup 1.0000x reference)
#include <cuda_runtime.h>
#include <cuda_bf16.h>
#include <cstdint>

#define BB 4
#define CC 64
#define HH 96
#define WW 96
#define TT 18
#define KK 9
#define OO 64
#define HWIMG (HH*WW)          // 9216
#define NPIX (BB*HWIMG)        // 36864
#define MT 128                 // pixels per tile
#define NTIL (NPIX/MT)         // 288

// -------- scratch (device globals) --------
__device__ float g_xn[NPIX * CC];                    // NHWC x
__device__ float g_offs[NPIX * TT];                  // [pix][18]
__device__ uint4 g_wdc4[(KK * 2 * OO * CC) / 8];     // bf16 swizzled [k][term][o:64][c:64]
__device__ uint4 g_woff4[(KK * 2 * 32 * CC) / 8];    // bf16 swizzled [k][term][o:32][c:64]

// ---------------- helpers ----------------
__device__ __forceinline__ uint32_t smem_u32(const void* p) {
    uint32_t a;
    asm("{ .reg .u64 t; cvta.to.shared.u64 t, %1; cvt.u32.u64 %0, t; }" : "=r"(a) : "l"(p));
    return a;
}
#define SWZ(b) ((b) ^ (((b) >> 3) & 0x70))

__device__ __forceinline__ uint32_t pack_bf16(float a, float b) {
    __nv_bfloat162 t = __floats2bfloat162_rn(a, b);   // .x=a (low half)
    return *(uint32_t*)&t;
}
// split s0,s1 into hi bf16x2 and lo bf16x2 (residual) using bit tricks
__device__ __forceinline__ void split2(float s0, float s1, uint32_t& hi, uint32_t& lo) {
    hi = pack_bf16(s0, s1);
    float h0 = __uint_as_float(hi << 16);
    float h1 = __uint_as_float(hi & 0xFFFF0000u);
    lo = pack_bf16(s0 - h0, s1 - h1);
}
#define STS64(a, r0, r1) asm volatile("st.shared.v2.b32 [%0], {%1,%2};" :: "r"(a), "r"(r0), "r"(r1) : "memory")

__device__ __forceinline__ void ldm4(uint32_t* r, uint32_t addr) {
    asm volatile("ldmatrix.sync.aligned.m8n8.x4.shared.b16 {%0,%1,%2,%3}, [%4];"
                 : "=r"(r[0]), "=r"(r[1]), "=r"(r[2]), "=r"(r[3]) : "r"(addr));
}
__device__ __forceinline__ void mma_bf16(float* c, const uint32_t* a, uint32_t b0, uint32_t b1) {
    asm volatile(
        "mma.sync.aligned.m16n8k16.row.col.f32.bf16.bf16.f32 "
        "{%0,%1,%2,%3}, {%4,%5,%6,%7}, {%8,%9}, {%0,%1,%2,%3};"
        : "+f"(c[0]), "+f"(c[1]), "+f"(c[2]), "+f"(c[3])
        : "r"(a[0]), "r"(a[1]), "r"(a[2]), "r"(a[3]), "r"(b0), "r"(b1));
}

// ---------------- NCHW -> NHWC transpose ----------------
__global__ void k_transpose(const float* __restrict__ x) {
    __shared__ float tile[64][97];
    int bh = blockIdx.x;
    int b = bh / HH;
    const float* src = x + ((size_t)b * CC) * HWIMG + (size_t)(bh % HH) * WW;
    for (int i = threadIdx.x; i < CC * WW; i += blockDim.x) {
        int c = i / WW, w = i % WW;
        tile[c][w] = src[(size_t)c * HWIMG + w];
    }
    __syncthreads();
    float* dst = g_xn + (size_t)bh * WW * CC;
    for (int i = threadIdx.x; i < WW * CC; i += blockDim.x) {
        int w = i / CC, c = i % CC;
        dst[i] = tile[c][w];
    }
}

// ---------------- weight repack: split bf16 hi/lo, pre-swizzled [o][c] rows ----------------
__global__ void k_repack(const float* __restrict__ w_off, const float* __restrict__ w_dc) {
    int i = blockIdx.x * blockDim.x + threadIdx.x;
    if (i < OO * CC * KK) {
        int o = i / (CC * KK);
        int r = i % (CC * KK);
        int c = r / KK;
        int k = r % KK;
        float v = w_dc[i];
        __nv_bfloat16 hi = __float2bfloat16(v);
        __nv_bfloat16 lo = __float2bfloat16(v - __bfloat162float(hi));
        uint32_t sw = SWZ((uint32_t)(o * 128 + c * 2));
        __nv_bfloat16* base = (__nv_bfloat16*)g_wdc4;
        base[(size_t)(k * 2 + 0) * 4096 + (sw >> 1)] = hi;
        base[(size_t)(k * 2 + 1) * 4096 + (sw >> 1)] = lo;
    }
    if (i < 32 * CC * KK) {
        int o = i / (CC * KK);
        int r = i % (CC * KK);
        int c = r / KK;
        int k = r % KK;
        float v = (o < TT) ? w_off[(size_t)o * CC * KK + c * KK + k] : 0.f;
        __nv_bfloat16 hi = __float2bfloat16(v);
        __nv_bfloat16 lo = __float2bfloat16(v - __bfloat162float(hi));
        uint32_t sw = SWZ((uint32_t)(o * 128 + c * 2));
        __nv_bfloat16* base = (__nv_bfloat16*)g_woff4;
        base[(size_t)(k * 2 + 0) * 2048 + (sw >> 1)] = hi;
        base[(size_t)(k * 2 + 1) * 2048 + (sw >> 1)] = lo;
    }
}

// ============== main deformable conv: param-phase + coalesced gather + mma.sync ==============
// smem: A 4x16KB (buf,term) = 65536 | W 2x16KB = 32768 | sP 2x4KB = 8192
#define MAIN_SW   65536
#define MAIN_SP   (MAIN_SW + 32768)
#define MAIN_SMEM (MAIN_SP + 8192)

__global__ void __launch_bounds__(256, 2) k_main_m(const float* __restrict__ b_dc,
                                                   float* __restrict__ out) {
    extern __shared__ __align__(1024) char smem[];
    uint32_t sb = smem_u32(smem);
    float* sP = (float*)(smem + MAIN_SP);   // [2][128][8] floats

    int tid = threadIdx.x;
    int wid = tid >> 5, lane = tid & 31;
    int wm = wid & 3, wn = wid >> 2;
    int m0 = wm * 32, n0 = wn * 32;

    int pix0 = blockIdx.x * MT;
    int b = pix0 / HWIMG, ip0 = pix0 % HWIMG;
    const float* xb = g_xn + (size_t)b * HWIMG * CC;
    const char* xb8 = (const char*)xb;
    int lpx = tid >> 4;      // pixel sub-index within pass
    int ck  = tid & 15;      // 16B channel chunk

    // per-thread (tid<128) pixel coords for the param phase
    int ph = 0, pw = 0;
    const float* goffp = g_offs;
    if (tid < 128) {
        int ip = ip0 + tid;
        ph = ip / WW; pw = ip - ph * WW;
        goffp = g_offs + (size_t)(pix0 + tid) * TT;
    }

    // hoisted swizzle bases
    uint32_t swbase;   // gather STS base (relative to A-plane base); safe: XOR before adding ps*2048
    {
        uint32_t chb = (uint32_t)((ck >> 1) * 16 + (ck & 1) * 8);
        swbase = ((uint32_t)(lpx * 128) + chb) ^ ((uint32_t)(lpx & 7) << 4);
    }
    // ldmatrix: rowbase + ((kt*32 + seg) ^ mask). mask = (lane&7)*16 for both A and B.
    uint32_t lmask = (uint32_t)(lane & 7) << 4;
    uint32_t arow[2], brow[2], segA, segB;
    {
        int rowoffA = ((lane >> 3) & 1) * 8 + (lane & 7);
        segA = (uint32_t)((lane >> 4) * 16);
#pragma unroll
        for (int mt = 0; mt < 2; mt++)
            arow[mt] = (uint32_t)((m0 + mt * 16 + rowoffA) * 128);
        int rowoffB = ((lane >> 4) & 1) * 8 + (lane & 7);
        segB = (uint32_t)(((lane >> 3) & 1) * 16);
#pragma unroll
        for (int ntp = 0; ntp < 2; ntp++)
            brow[ntp] = (uint32_t)((n0 + ntp * 16 + rowoffB) * 128);
    }

    float acc[2][4][4];
#pragma unroll
    for (int nt = 0; nt < 4; nt++) {
        int o = n0 + nt * 8 + (lane & 3) * 2;
        float b0v = b_dc[o], b1v = b_dc[o + 1];
#pragma unroll
        for (int mt = 0; mt < 2; mt++) {
            acc[mt][nt][0] = b0v; acc[mt][nt][1] = b1v;
            acc[mt][nt][2] = b0v; acc[mt][nt][3] = b1v;
        }
    }

#define PARAMS(KI, PB) do {                                                        \
        float2 dxy = *(const float2*)(goffp + 2 * (KI));                           \
        float py  = (float)(ph + (KI) / 3 - 1) + dxy.x;                            \
        float pxx = (float)(pw + (KI) % 3 - 1) + dxy.y;                            \
        float y0f = floorf(py), x0f = floorf(pxx);                                 \
        float ly = py - y0f, lx = pxx - x0f;                                       \
        int y0 = (int)y0f, x0 = (int)x0f, y1 = y0 + 1, x1 = x0 + 1;                \
        float w00 = (1.f - ly) * (1.f - lx), w01 = (1.f - ly) * lx;                \
        float w10 = ly * (1.f - lx), w11 = ly * lx;                                \
        bool vy0 = (unsigned)y0 < HH, vy1 = (unsigned)y1 < HH;                     \
        bool vx0 = (unsigned)x0 < WW, vx1 = (unsigned)x1 < WW;                     \
        w00 *= (float)(vy0 && vx0); w01 *= (float)(vy0 && vx1);                    \
        w10 *= (float)(vy1 && vx0); w11 *= (float)(vy1 && vx1);                    \
        int yc0 = min(max(y0, 0), HH - 1), yc1 = min(max(y1, 0), HH - 1);          \
        int xc0 = min(max(x0, 0), WW - 1), xc1 = min(max(x1, 0), WW - 1);          \
        float4* p = (float4*)(sP + (PB) * 1024) + tid * 2;                         \
        p[0] = make_float4(w00, w01, w10, w11);                                    \
        p[1] = make_float4(__int_as_float((yc0 * WW + xc0) * (CC * 4)),            \
                           __int_as_float((yc0 * WW + xc1) * (CC * 4)),            \
                           __int_as_float((yc1 * WW + xc0) * (CC * 4)),            \
                           __int_as_float((yc1 * WW + xc1) * (CC * 4)));           \
    } while (0)

#define GATHER(BUF, PB) do {                                                       \
        uint32_t abase_h = sb + ((BUF) * 2 + 0) * 16384 + swbase;                  \
        uint32_t abase_l = sb + ((BUF) * 2 + 1) * 16384 + swbase;                  \
        const float4* sPp = (const float4*)(sP + (PB) * 1024);                     \
        _Pragma("unroll")                                                          \
        for (int ps = 0; ps < 8; ps++) {                                           \
            const float4* pp = sPp + (ps * 16 + lpx) * 2;                          \
            float4 wv = pp[0], iv = pp[1];                                         \
            float4 a4 = ((const float4*)(xb8 + __float_as_int(iv.x)))[ck];         \
            float4 b4 = ((const float4*)(xb8 + __float_as_int(iv.y)))[ck];         \
            float4 c4 = ((const float4*)(xb8 + __float_as_int(iv.z)))[ck];         \
            float4 d4 = ((const float4*)(xb8 + __float_as_int(iv.w)))[ck];         \
            float s0 = wv.x * a4.x + wv.y * b4.x + wv.z * c4.x + wv.w * d4.x;      \
            float s1 = wv.x * a4.y + wv.y * b4.y + wv.z * c4.y + wv.w * d4.y;      \
            float s2 = wv.x * a4.z + wv.y * b4.z + wv.z * c4.z + wv.w * d4.z;      \
            float s3 = wv.x * a4.w + wv.y * b4.w + wv.z * c4.w + wv.w * d4.w;      \
            uint32_t hiA, loA, hiB, loB;                                           \
            split2(s0, s1, hiA, loA);                                              \
            split2(s2, s3, hiB, loB);                                              \
            STS64(abase_h + ps * 2048, hiA, hiB);                                  \
            STS64(abase_l + ps * 2048, loA, loB);                                  \
        }                                                                          \
    } while (0)

#define WCOPYW(KI, BUF) do {                                                       \
        const uint4* srcw = g_wdc4 + (size_t)(KI) * 1024;                          \
        uint4* dstw = (uint4*)(smem + MAIN_SW + (BUF) * 16384);                    \
        for (int i = tid - 128; i < 1024; i += 128) dstw[i] = srcw[i];             \
    } while (0)

    if (tid < 128) PARAMS(0, 0);
    else           WCOPYW(0, 0);
    __syncthreads();
    GATHER(0, 0);
    if (tid < 128) PARAMS(1, 1);
    __syncthreads();

#pragma unroll 1
    for (int k = 0; k < KK; k++) {
        int buf = k & 1;
        if (tid < 128) {
            if (k < KK - 2) PARAMS(k + 2, buf);
        } else {
            if (k < KK - 1) WCOPYW(k + 1, buf ^ 1);
        }
        // ---- mma for tap k ----
        uint32_t abH = sb + (buf * 2 + 0) * 16384;
        uint32_t abL = sb + (buf * 2 + 1) * 16384;
        uint32_t wbH = sb + MAIN_SW + buf * 16384;
        uint32_t wbL = wbH + 8192;
#pragma unroll
        for (int kt = 0; kt < 4; kt++) {
            uint32_t colA = ((uint32_t)(kt * 32) + segA) ^ lmask;
            uint32_t colB = ((uint32_t)(kt * 32) + segB) ^ lmask;
            uint32_t aH[2][4], aL[2][4], bH[2][4], bL[2][4];
#pragma unroll
            for (int mt = 0; mt < 2; mt++) {
                ldm4(aH[mt], abH + arow[mt] + colA);
                ldm4(aL[mt], abL + arow[mt] + colA);
            }
#pragma unroll
            for (int ntp = 0; ntp < 2; ntp++) {
                ldm4(bH[ntp], wbH + brow[ntp] + colB);
                ldm4(bL[ntp], wbL + brow[ntp] + colB);
            }
#pragma unroll
            for (int mt = 0; mt < 2; mt++)
#pragma unroll
                for (int nt = 0; nt < 4; nt++) {
                    int ntp = nt >> 1, hi2 = (nt & 1) * 2;
                    mma_bf16(acc[mt][nt], aH[mt], bH[ntp][hi2], bH[ntp][hi2 + 1]);
                    mma_bf16(acc[mt][nt], aH[mt], bL[ntp][hi2], bL[ntp][hi2 + 1]);
                    mma_bf16(acc[mt][nt], aL[mt], bH[ntp][hi2], bH[ntp][hi2 + 1]);
                }
        }
        if (k < KK - 1) GATHER(buf ^ 1, (k + 1) & 1);
        __syncthreads();
    }

    // epilogue: transpose via smem, coalesced NCHW float4 stores
    float* oT = (float*)smem;   // [64][132]
#pragma unroll
    for (int mt = 0; mt < 2; mt++)
#pragma unroll
        for (int nt = 0; nt < 4; nt++) {
            int o = n0 + nt * 8 + (lane & 3) * 2;
            int p = m0 + mt * 16 + (lane >> 2);
            oT[o * 132 + p]           = acc[mt][nt][0];
            oT[(o + 1) * 132 + p]     = acc[mt][nt][1];
            oT[o * 132 + p + 8]       = acc[mt][nt][2];
            oT[(o + 1) * 132 + p + 8] = acc[mt][nt][3];
        }
    __syncthreads();
    {
        size_t obase = (size_t)b * OO * HWIMG + ip0;
        for (int i = tid; i < OO * (MT / 4); i += 256) {
            int o = i >> 5, p4 = i & 31;
            float4 v = *(const float4*)(oT + o * 132 + p4 * 4);
            *(float4*)(out + obase + (size_t)o * HWIMG + p4 * 4) = v;
        }
    }
#undef PARAMS
#undef GATHER
#undef WCOPYW
}

// ============== offset conv: param-phase + coalesced shift-gather + mma.sync (N=32) ==============
// smem: A 4x16KB = 65536 | W 2x8KB = 16384 | sPo 2KB
#define OFF_SW   65536
#define OFF_SP   (OFF_SW + 16384)
#define OFF_SMEM (OFF_SP + 2048)

__global__ void __launch_bounds__(256, 2) k_off_m(const float* __restrict__ b_off) {
    extern __shared__ __align__(1024) char smem[];
    uint32_t sb = smem_u32(smem);
    float* sPo = (float*)(smem + OFF_SP);   // [2][128][2]

    int tid = threadIdx.x;
    int wid = tid >> 5, lane = tid & 31;
    int m0 = wid * 16;

    int pix0 = blockIdx.x * MT;
    int b = pix0 / HWIMG, ip0 = pix0 % HWIMG;
    const float* xb = g_xn + (size_t)b * HWIMG * CC;
    const char* xb8 = (const char*)xb;
    int lpx = tid >> 4, ck = tid & 15;

    int ph = 0, pw = 0;
    if (tid < 128) {
        int ip = ip0 + tid;
        ph = ip / WW; pw = ip - ph * WW;
    }

    uint32_t swbase;
    {
        uint32_t chb = (uint32_t)((ck >> 1) * 16 + (ck & 1) * 8);
        swbase = ((uint32_t)(lpx * 128) + chb) ^ ((uint32_t)(lpx & 7) << 4);
    }
    uint32_t lmask = (uint32_t)(lane & 7) << 4;
    uint32_t arowo, browo[2], segAo, segBo;
    {
        int rowoffA = ((lane >> 3) & 1) * 8 + (lane & 7);
        segAo = (uint32_t)((lane >> 4) * 16);
        arowo = (uint32_t)((m0 + rowoffA) * 128);
        int rowoffB = ((lane >> 4) & 1) * 8 + (lane & 7);
        segBo = (uint32_t)(((lane >> 3) & 1) * 16);
#pragma unroll
        for (int ntp = 0; ntp < 2; ntp++)
            browo[ntp] = (uint32_t)((ntp * 16 + rowoffB) * 128);
    }

    float acc[4][4];
#pragma unroll
    for (int nt = 0; nt < 4; nt++) {
        int o = nt * 8 + (lane & 3) * 2;
        float b0v = (o < TT) ? b_off[o] : 0.f;
        float b1v = (o + 1 < TT) ? b_off[o + 1] : 0.f;
        acc[nt][0] = b0v; acc[nt][1] = b1v;
        acc[nt][2] = b0v; acc[nt][3] = b1v;
    }

#define POFF(KI, PB) do {                                                          \
        int y = ph + (KI) / 3 - 1, x = pw + (KI) % 3 - 1;                          \
        float vm = ((unsigned)y < HH && (unsigned)x < WW) ? 1.f : 0.f;             \
        int yc = min(max(y, 0), HH - 1), xc = min(max(x, 0), WW - 1);              \
        float2* p = (float2*)(sPo + (PB) * 256) + tid;                             \
        *p = make_float2(vm, __int_as_float((yc * WW + xc) * (CC * 4)));           \
    } while (0)

#define GATHS(BUF, PB) do {                                                        \
        uint32_t abase_h = sb + ((BUF) * 2 + 0) * 16384 + swbase;                  \
        uint32_t abase_l = sb + ((BUF) * 2 + 1) * 16384 + swbase;                  \
        const float2* sPp = (const float2*)(sPo + (PB) * 256);                     \
        _Pragma("unroll")                                                          \
        for (int ps = 0; ps < 8; ps++) {                                           \
            float2 pv = sPp[ps * 16 + lpx];                                        \
            float4 v4 = ((const float4*)(xb8 + __float_as_int(pv.y)))[ck];         \
            float s0 = v4.x * pv.x, s1 = v4.y * pv.x;                              \
            float s2 = v4.z * pv.x, s3 = v4.w * pv.x;                              \
            uint32_t hiA, loA, hiB, loB;                                           \
            split2(s0, s1, hiA, loA);                                              \
            split2(s2, s3, hiB, loB);                                              \
            STS64(abase_h + ps * 2048, hiA, hiB);                                  \
            STS64(abase_l + ps * 2048, loA, loB);                                  \
        }                                                                          \
    } while (0)

#define WCOPYO(KI, BUF) do {                                                       \
        const uint4* srcw = g_woff4 + (size_t)(KI) * 512;                          \
        uint4* dstw = (uint4*)(smem + OFF_SW + (BUF) * 8192);                      \
        for (int i = tid - 128; i < 512; i += 128) dstw[i] = srcw[i];              \
    } while (0)

    if (tid < 128) POFF(0, 0);
    else           WCOPYO(0, 0);
    __syncthreads();
    GATHS(0, 0);
    if (tid < 128) POFF(1, 1);
    __syncthreads();

#pragma unroll 1
    for (int k = 0; k < KK; k++) {
        int buf = k & 1;
        if (tid < 128) {
            if (k < KK - 2) POFF(k + 2, buf);
        } else {
            if (k < KK - 1) WCOPYO(k + 1, buf ^ 1);
        }
        uint32_t abH = sb + (buf * 2 + 0) * 16384;
        uint32_t abL = sb + (buf * 2 + 1) * 16384;
        uint32_t wbH = sb + OFF_SW + buf * 8192;
        uint32_t wbL = wbH + 4096;
#pragma unroll
        for (int kt = 0; kt < 4; kt++) {
            uint32_t colA = ((uint32_t)(kt * 32) + segAo) ^ lmask;
            uint32_t colB = ((uint32_t)(kt * 32) + segBo) ^ lmask;
            uint32_t aH[4], aL[4], bH[2][4], bL[2][4];
            ldm4(aH, abH + arowo + colA);
            ldm4(aL, abL + arowo + colA);
#pragma unroll
            for (int ntp = 0; ntp < 2; ntp++) {
                ldm4(bH[ntp], wbH + browo[ntp] + colB);
                ldm4(bL[ntp], wbL + browo[ntp] + colB);
            }
#pragma unroll
            for (int nt = 0; nt < 4; nt++) {
                int ntp = nt >> 1, hi2 = (nt & 1) * 2;
                mma_bf16(acc[nt], aH, bH[ntp][hi2], bH[ntp][hi2 + 1]);
                mma_bf16(acc[nt], aH, bL[ntp][hi2], bL[ntp][hi2 + 1]);
                mma_bf16(acc[nt], aL, bH[ntp][hi2], bH[ntp][hi2 + 1]);
            }
        }
        if (k < KK - 1) GATHS(buf ^ 1, (k + 1) & 1);
        __syncthreads();
    }

    // epilogue: oT[p][o] stride 20, then pack to g_offs[pix][18]
    float* oT = (float*)smem;   // [128][20]
#pragma unroll
    for (int nt = 0; nt < 4; nt++) {
        int o = nt * 8 + (lane & 3) * 2;
        int p = m0 + (lane >> 2);
        if (o < TT) {
            oT[p * 20 + o] = acc[nt][0];
            oT[(p + 8) * 20 + o] = acc[nt][2];
        }
        if (o + 1 < TT) {
            oT[p * 20 + o + 1] = acc[nt][1];
            oT[(p + 8) * 20 + o + 1] = acc[nt][3];
        }
    }
    __syncthreads();
    {
        float* dst = g_offs + (size_t)pix0 * TT;
        for (int i = tid; i < MT * TT; i += 256)
            dst[i] = oT[(i / TT) * 20 + (i % TT)];
    }
#undef POFF
#undef GATHS
#undef WCOPYO
}

// ---------------- launch ----------------
extern "C" void kernel_launch(void* const* d_in, const int* in_sizes, int n_in,
                              void* d_out, int out_size) {
    const float* x     = (const float*)d_in[0];
    const float* w_off = (const float*)d_in[1];
    const float* b_off = (const float*)d_in[2];
    const float* w_dc  = (const float*)d_in[3];
    const float* b_dc  = (const float*)d_in[4];
    float* out = (float*)d_out;

    cudaFuncSetAttribute(k_off_m, cudaFuncAttributeMaxDynamicSharedMemorySize, OFF_SMEM);
    cudaFuncSetAttribute(k_main_m, cudaFuncAttributeMaxDynamicSharedMemorySize, MAIN_SMEM);

    k_transpose<<<BB * HH, 256>>>(x);
    k_repack<<<(OO * CC * KK + 255) / 256, 256>>>(w_off, w_dc);
    k_off_m<<<NTIL, 256, OFF_SMEM>>>(b_off);
    k_main_m<<<NTIL, 256, MAIN_SMEM>>>(b_dc, out);
}

// round 8
// speedup vs baseline: 1.0408x; 1.0408x over previous
#include <cuda_runtime.h>
#include <cuda_bf16.h>
#include <cstdint>

#define BB 4
#define CC 64
#define HH 96
#define WW 96
#define TT 18
#define KK 9
#define OO 64
#define HWIMG (HH*WW)          // 9216
#define NPIX (BB*HWIMG)        // 36864
#define MT 128                 // pixels per tile
#define NTIL (NPIX/MT)         // 288

// -------- scratch (device globals) --------
__device__ float g_xn[NPIX * CC];                    // NHWC x
__device__ float g_offs[NPIX * TT];                  // [pix][18]
__device__ uint4 g_wdc4[(KK * 2 * OO * CC) / 8];     // bf16 swizzled [k][term][o:64][c:64]
__device__ uint4 g_woff4[(KK * 2 * 32 * CC) / 8];    // bf16 swizzled [k][term][o:32][c:64]

// ---------------- helpers ----------------
__device__ __forceinline__ uint32_t smem_u32(const void* p) {
    uint32_t a;
    asm("{ .reg .u64 t; cvta.to.shared.u64 t, %1; cvt.u32.u64 %0, t; }" : "=r"(a) : "l"(p));
    return a;
}
#define SWZ(b) ((b) ^ (((b) >> 3) & 0x70))

__device__ __forceinline__ uint32_t pack_bf16(float a, float b) {
    __nv_bfloat162 t = __floats2bfloat162_rn(a, b);   // .x=a (low half)
    return *(uint32_t*)&t;
}
__device__ __forceinline__ void split2(float s0, float s1, uint32_t& hi, uint32_t& lo) {
    hi = pack_bf16(s0, s1);
    float h0 = __uint_as_float(hi << 16);
    float h1 = __uint_as_float(hi & 0xFFFF0000u);
    lo = pack_bf16(s0 - h0, s1 - h1);
}
#define STS64(a, r0, r1) asm volatile("st.shared.v2.b32 [%0], {%1,%2};" :: "r"(a), "r"(r0), "r"(r1) : "memory")

__device__ __forceinline__ void ldm4(uint32_t* r, uint32_t addr) {
    asm volatile("ldmatrix.sync.aligned.m8n8.x4.shared.b16 {%0,%1,%2,%3}, [%4];"
                 : "=r"(r[0]), "=r"(r[1]), "=r"(r[2]), "=r"(r[3]) : "r"(addr));
}
__device__ __forceinline__ void mma_bf16(float* c, const uint32_t* a, uint32_t b0, uint32_t b1) {
    asm volatile(
        "mma.sync.aligned.m16n8k16.row.col.f32.bf16.bf16.f32 "
        "{%0,%1,%2,%3}, {%4,%5,%6,%7}, {%8,%9}, {%0,%1,%2,%3};"
        : "+f"(c[0]), "+f"(c[1]), "+f"(c[2]), "+f"(c[3])
        : "r"(a[0]), "r"(a[1]), "r"(a[2]), "r"(a[3]), "r"(b0), "r"(b1));
}

// ---------------- prep: transpose (blocks 0..383) + weight repack (blocks 384..527) ----------------
__global__ void k_prep(const float* __restrict__ x,
                       const float* __restrict__ w_off, const float* __restrict__ w_dc) {
    if (blockIdx.x < BB * HH) {
        __shared__ float tile[64][97];
        int bh = blockIdx.x;
        int b = bh / HH;
        const float* src = x + ((size_t)b * CC) * HWIMG + (size_t)(bh % HH) * WW;
        for (int i = threadIdx.x; i < CC * WW; i += blockDim.x) {
            int c = i / WW, w = i % WW;
            tile[c][w] = src[(size_t)c * HWIMG + w];
        }
        __syncthreads();
        float* dst = g_xn + (size_t)bh * WW * CC;
        for (int i = threadIdx.x; i < WW * CC; i += blockDim.x) {
            int w = i / CC, c = i % CC;
            dst[i] = tile[c][w];
        }
    } else {
        int i = (blockIdx.x - BB * HH) * 256 + threadIdx.x;
        if (i < OO * CC * KK) {
            int o = i / (CC * KK);
            int r = i % (CC * KK);
            int c = r / KK;
            int k = r % KK;
            float v = w_dc[i];
            __nv_bfloat16 hi = __float2bfloat16(v);
            __nv_bfloat16 lo = __float2bfloat16(v - __bfloat162float(hi));
            uint32_t sw = SWZ((uint32_t)(o * 128 + c * 2));
            __nv_bfloat16* base = (__nv_bfloat16*)g_wdc4;
            base[(size_t)(k * 2 + 0) * 4096 + (sw >> 1)] = hi;
            base[(size_t)(k * 2 + 1) * 4096 + (sw >> 1)] = lo;
        }
        if (i < 32 * CC * KK) {
            int o = i / (CC * KK);
            int r = i % (CC * KK);
            int c = r / KK;
            int k = r % KK;
            float v = (o < TT) ? w_off[(size_t)o * CC * KK + c * KK + k] : 0.f;
            __nv_bfloat16 hi = __float2bfloat16(v);
            __nv_bfloat16 lo = __float2bfloat16(v - __bfloat162float(hi));
            uint32_t sw = SWZ((uint32_t)(o * 128 + c * 2));
            __nv_bfloat16* base = (__nv_bfloat16*)g_woff4;
            base[(size_t)(k * 2 + 0) * 2048 + (sw >> 1)] = hi;
            base[(size_t)(k * 2 + 1) * 2048 + (sw >> 1)] = lo;
        }
    }
}

// ============== fused offset-conv + deformable conv ==============
// smem: A 4x16KB (buf,term) = 65536 | W 2x16KB = 32768 | sP 8KB
#define MAIN_SW   65536
#define MAIN_SP   (MAIN_SW + 32768)
#define MAIN_SMEM (MAIN_SP + 8192)

__global__ void __launch_bounds__(256, 2) k_fused(const float* __restrict__ b_off,
                                                  const float* __restrict__ b_dc,
                                                  float* __restrict__ out) {
    extern __shared__ __align__(1024) char smem[];
    uint32_t sb = smem_u32(smem);
    float* sP = (float*)(smem + MAIN_SP);   // phase A: [2][128][2]; phase B: [2][128][8]

    int tid = threadIdx.x;
    int wid = tid >> 5, lane = tid & 31;

    int pix0 = blockIdx.x * MT;
    int b = pix0 / HWIMG, ip0 = pix0 % HWIMG;
    const float* xb = g_xn + (size_t)b * HWIMG * CC;
    const char* xb8 = (const char*)xb;
    int lpx = tid >> 4;      // pixel sub-index within gather pass
    int ck  = tid & 15;      // 16B channel chunk

    int ph = 0, pw = 0;
    if (tid < 128) {
        int ip = ip0 + tid;
        ph = ip / WW; pw = ip - ph * WW;
    }

    // gather STS swizzle base (XOR applied before adding ps*2048 — safe)
    uint32_t swbase;
    {
        uint32_t chb = (uint32_t)((ck >> 1) * 16 + (ck & 1) * 8);
        swbase = ((uint32_t)(lpx * 128) + chb) ^ ((uint32_t)(lpx & 7) << 4);
    }
    uint32_t lmask = (uint32_t)(lane & 7) << 4;

    // ===================== PHASE A: offset conv (N=32) =====================
    {
        int m0 = wid * 16;
        uint32_t arowo, browo[2], segAo, segBo;
        {
            int rowoffA = ((lane >> 3) & 1) * 8 + (lane & 7);
            segAo = (uint32_t)((lane >> 4) * 16);
            arowo = (uint32_t)((m0 + rowoffA) * 128);
            int rowoffB = ((lane >> 4) & 1) * 8 + (lane & 7);
            segBo = (uint32_t)(((lane >> 3) & 1) * 16);
#pragma unroll
            for (int ntp = 0; ntp < 2; ntp++)
                browo[ntp] = (uint32_t)((ntp * 16 + rowoffB) * 128);
        }

        float acc[4][4];
#pragma unroll
        for (int nt = 0; nt < 4; nt++) {
            int o = nt * 8 + (lane & 3) * 2;
            float b0v = (o < TT) ? b_off[o] : 0.f;
            float b1v = (o + 1 < TT) ? b_off[o + 1] : 0.f;
            acc[nt][0] = b0v; acc[nt][1] = b1v;
            acc[nt][2] = b0v; acc[nt][3] = b1v;
        }

#define POFF(KI, PB) do {                                                          \
        int y = ph + (KI) / 3 - 1, x = pw + (KI) % 3 - 1;                          \
        float vm = ((unsigned)y < HH && (unsigned)x < WW) ? 1.f : 0.f;             \
        int yc = min(max(y, 0), HH - 1), xc = min(max(x, 0), WW - 1);              \
        float2* p = (float2*)(sP + (PB) * 256) + tid;                              \
        *p = make_float2(vm, __int_as_float((yc * WW + xc) * (CC * 4)));           \
    } while (0)

#define GATHS(BUF, PB) do {                                                        \
        uint32_t abase_h = sb + ((BUF) * 2 + 0) * 16384 + swbase;                  \
        uint32_t abase_l = sb + ((BUF) * 2 + 1) * 16384 + swbase;                  \
        const float2* sPp = (const float2*)(sP + (PB) * 256);                      \
        _Pragma("unroll")                                                          \
        for (int ps = 0; ps < 8; ps++) {                                           \
            float2 pv = sPp[ps * 16 + lpx];                                        \
            float4 v4 = ((const float4*)(xb8 + __float_as_int(pv.y)))[ck];         \
            float s0 = v4.x * pv.x, s1 = v4.y * pv.x;                              \
            float s2 = v4.z * pv.x, s3 = v4.w * pv.x;                              \
            uint32_t hiA, loA, hiB, loB;                                           \
            split2(s0, s1, hiA, loA);                                              \
            split2(s2, s3, hiB, loB);                                              \
            STS64(abase_h + ps * 2048, hiA, hiB);                                  \
            STS64(abase_l + ps * 2048, loA, loB);                                  \
        }                                                                          \
    } while (0)

#define WCOPYO(KI, BUF) do {                                                       \
        const uint4* srcw = g_woff4 + (size_t)(KI) * 512;                          \
        uint4* dstw = (uint4*)(smem + MAIN_SW + (BUF) * 8192);                     \
        for (int i = tid - 128; i < 512; i += 128) dstw[i] = srcw[i];              \
    } while (0)

        if (tid < 128) POFF(0, 0);
        else           WCOPYO(0, 0);
        __syncthreads();
        GATHS(0, 0);
        if (tid < 128) POFF(1, 1);
        __syncthreads();

#pragma unroll 1
        for (int k = 0; k < KK; k++) {
            int buf = k & 1;
            if (tid < 128) {
                if (k < KK - 2) POFF(k + 2, buf);
            } else {
                if (k < KK - 1) WCOPYO(k + 1, buf ^ 1);
            }
            uint32_t abH = sb + (buf * 2 + 0) * 16384;
            uint32_t abL = sb + (buf * 2 + 1) * 16384;
            uint32_t wbH = sb + MAIN_SW + buf * 8192;
            uint32_t wbL = wbH + 4096;
#pragma unroll
            for (int kt = 0; kt < 4; kt++) {
                uint32_t colA = ((uint32_t)(kt * 32) + segAo) ^ lmask;
                uint32_t colB = ((uint32_t)(kt * 32) + segBo) ^ lmask;
                uint32_t aH[4], aL[4], bH[2][4], bL[2][4];
                ldm4(aH, abH + arowo + colA);
                ldm4(aL, abL + arowo + colA);
#pragma unroll
                for (int ntp = 0; ntp < 2; ntp++) {
                    ldm4(bH[ntp], wbH + browo[ntp] + colB);
                    ldm4(bL[ntp], wbL + browo[ntp] + colB);
                }
#pragma unroll
                for (int nt = 0; nt < 4; nt++) {
                    int ntp = nt >> 1, hi2 = (nt & 1) * 2;
                    mma_bf16(acc[nt], aH, bH[ntp][hi2], bH[ntp][hi2 + 1]);
                    mma_bf16(acc[nt], aH, bL[ntp][hi2], bL[ntp][hi2 + 1]);
                    mma_bf16(acc[nt], aL, bH[ntp][hi2], bH[ntp][hi2 + 1]);
                }
            }
            if (k < KK - 1) GATHS(buf ^ 1, (k + 1) & 1);
            __syncthreads();
        }

        // epilogue A: oT[p][o] stride 20 -> g_offs[pix][18]
        float* oT = (float*)smem;   // [128][20]
#pragma unroll
        for (int nt = 0; nt < 4; nt++) {
            int o = nt * 8 + (lane & 3) * 2;
            int p = m0 + (lane >> 2);
            if (o < TT) {
                oT[p * 20 + o] = acc[nt][0];
                oT[(p + 8) * 20 + o] = acc[nt][2];
            }
            if (o + 1 < TT) {
                oT[p * 20 + o + 1] = acc[nt][1];
                oT[(p + 8) * 20 + o + 1] = acc[nt][3];
            }
        }
        __syncthreads();
        {
            float* dst = g_offs + (size_t)pix0 * TT;
            for (int i = tid; i < MT * TT; i += 256)
                dst[i] = oT[(i / TT) * 20 + (i % TT)];
        }
#undef POFF
#undef GATHS
#undef WCOPYO
    }
    __syncthreads();   // g_offs visible block-wide; smem free for phase B

    // ===================== PHASE B: main deformable conv (N=64) =====================
    {
        int wm = wid & 3, wn = wid >> 2;
        int m0 = wm * 32, n0 = wn * 32;
        const float* goffp = g_offs;
        if (tid < 128) goffp = g_offs + (size_t)(pix0 + tid) * TT;

        uint32_t arow[2], brow[2], segA, segB;
        {
            int rowoffA = ((lane >> 3) & 1) * 8 + (lane & 7);
            segA = (uint32_t)((lane >> 4) * 16);
#pragma unroll
            for (int mt = 0; mt < 2; mt++)
                arow[mt] = (uint32_t)((m0 + mt * 16 + rowoffA) * 128);
            int rowoffB = ((lane >> 4) & 1) * 8 + (lane & 7);
            segB = (uint32_t)(((lane >> 3) & 1) * 16);
#pragma unroll
            for (int ntp = 0; ntp < 2; ntp++)
                brow[ntp] = (uint32_t)((n0 + ntp * 16 + rowoffB) * 128);
        }

        float acc[2][4][4];
#pragma unroll
        for (int nt = 0; nt < 4; nt++) {
            int o = n0 + nt * 8 + (lane & 3) * 2;
            float b0v = b_dc[o], b1v = b_dc[o + 1];
#pragma unroll
            for (int mt = 0; mt < 2; mt++) {
                acc[mt][nt][0] = b0v; acc[mt][nt][1] = b1v;
                acc[mt][nt][2] = b0v; acc[mt][nt][3] = b1v;
            }
        }

#define PARAMS(KI, PB) do {                                                        \
        float2 dxy = *(const float2*)(goffp + 2 * (KI));                           \
        float py  = (float)(ph + (KI) / 3 - 1) + dxy.x;                            \
        float pxx = (float)(pw + (KI) % 3 - 1) + dxy.y;                            \
        float y0f = floorf(py), x0f = floorf(pxx);                                 \
        float ly = py - y0f, lx = pxx - x0f;                                       \
        int y0 = (int)y0f, x0 = (int)x0f, y1 = y0 + 1, x1 = x0 + 1;                \
        float w00 = (1.f - ly) * (1.f - lx), w01 = (1.f - ly) * lx;                \
        float w10 = ly * (1.f - lx), w11 = ly * lx;                                \
        bool vy0 = (unsigned)y0 < HH, vy1 = (unsigned)y1 < HH;                     \
        bool vx0 = (unsigned)x0 < WW, vx1 = (unsigned)x1 < WW;                     \
        w00 *= (float)(vy0 && vx0); w01 *= (float)(vy0 && vx1);                    \
        w10 *= (float)(vy1 && vx0); w11 *= (float)(vy1 && vx1);                    \
        int yc0 = min(max(y0, 0), HH - 1), yc1 = min(max(y1, 0), HH - 1);          \
        int xc0 = min(max(x0, 0), WW - 1), xc1 = min(max(x1, 0), WW - 1);          \
        float4* p = (float4*)(sP + (PB) * 1024) + tid * 2;                         \
        p[0] = make_float4(w00, w01, w10, w11);                                    \
        p[1] = make_float4(__int_as_float((yc0 * WW + xc0) * (CC * 4)),            \
                           __int_as_float((yc0 * WW + xc1) * (CC * 4)),            \
                           __int_as_float((yc1 * WW + xc0) * (CC * 4)),            \
                           __int_as_float((yc1 * WW + xc1) * (CC * 4)));           \
    } while (0)

#define GATHER(BUF, PB) do {                                                       \
        uint32_t abase_h = sb + ((BUF) * 2 + 0) * 16384 + swbase;                  \
        uint32_t abase_l = sb + ((BUF) * 2 + 1) * 16384 + swbase;                  \
        const float4* sPp = (const float4*)(sP + (PB) * 1024);                     \
        _Pragma("unroll")                                                          \
        for (int ps = 0; ps < 8; ps++) {                                           \
            const float4* pp = sPp + (ps * 16 + lpx) * 2;                          \
            float4 wv = pp[0], iv = pp[1];                                         \
            float4 a4 = ((const float4*)(xb8 + __float_as_int(iv.x)))[ck];         \
            float4 b4 = ((const float4*)(xb8 + __float_as_int(iv.y)))[ck];         \
            float4 c4 = ((const float4*)(xb8 + __float_as_int(iv.z)))[ck];         \
            float4 d4 = ((const float4*)(xb8 + __float_as_int(iv.w)))[ck];         \
            float s0 = wv.x * a4.x + wv.y * b4.x + wv.z * c4.x + wv.w * d4.x;      \
            float s1 = wv.x * a4.y + wv.y * b4.y + wv.z * c4.y + wv.w * d4.y;      \
            float s2 = wv.x * a4.z + wv.y * b4.z + wv.z * c4.z + wv.w * d4.z;      \
            float s3 = wv.x * a4.w + wv.y * b4.w + wv.z * c4.w + wv.w * d4.w;      \
            uint32_t hiA, loA, hiB, loB;                                           \
            split2(s0, s1, hiA, loA);                                              \
            split2(s2, s3, hiB, loB);                                              \
            STS64(abase_h + ps * 2048, hiA, hiB);                                  \
            STS64(abase_l + ps * 2048, loA, loB);                                  \
        }                                                                          \
    } while (0)

#define WCOPYW(KI, BUF) do {                                                       \
        const uint4* srcw = g_wdc4 + (size_t)(KI) * 1024;                          \
        uint4* dstw = (uint4*)(smem + MAIN_SW + (BUF) * 16384);                    \
        for (int i = tid - 128; i < 1024; i += 128) dstw[i] = srcw[i];             \
    } while (0)

        if (tid < 128) PARAMS(0, 0);
        else           WCOPYW(0, 0);
        __syncthreads();
        GATHER(0, 0);
        if (tid < 128) PARAMS(1, 1);
        __syncthreads();

#pragma unroll 1
        for (int k = 0; k < KK; k++) {
            int buf = k & 1;
            if (tid < 128) {
                if (k < KK - 2) PARAMS(k + 2, buf);
            } else {
                if (k < KK - 1) WCOPYW(k + 1, buf ^ 1);
            }
            uint32_t abH = sb + (buf * 2 + 0) * 16384;
            uint32_t abL = sb + (buf * 2 + 1) * 16384;
            uint32_t wbH = sb + MAIN_SW + buf * 16384;
            uint32_t wbL = wbH + 8192;
#pragma unroll
            for (int kt = 0; kt < 4; kt++) {
                uint32_t colA = ((uint32_t)(kt * 32) + segA) ^ lmask;
                uint32_t colB = ((uint32_t)(kt * 32) + segB) ^ lmask;
                uint32_t aH[2][4], aL[2][4], bH[2][4], bL[2][4];
#pragma unroll
                for (int mt = 0; mt < 2; mt++) {
                    ldm4(aH[mt], abH + arow[mt] + colA);
                    ldm4(aL[mt], abL + arow[mt] + colA);
                }
#pragma unroll
                for (int ntp = 0; ntp < 2; ntp++) {
                    ldm4(bH[ntp], wbH + brow[ntp] + colB);
                    ldm4(bL[ntp], wbL + brow[ntp] + colB);
                }
#pragma unroll
                for (int mt = 0; mt < 2; mt++)
#pragma unroll
                    for (int nt = 0; nt < 4; nt++) {
                        int ntp = nt >> 1, hi2 = (nt & 1) * 2;
                        mma_bf16(acc[mt][nt], aH[mt], bH[ntp][hi2], bH[ntp][hi2 + 1]);
                        mma_bf16(acc[mt][nt], aH[mt], bL[ntp][hi2], bL[ntp][hi2 + 1]);
                        mma_bf16(acc[mt][nt], aL[mt], bH[ntp][hi2], bH[ntp][hi2 + 1]);
                    }
            }
            if (k < KK - 1) GATHER(buf ^ 1, (k + 1) & 1);
            __syncthreads();
        }

        // epilogue B: transpose via smem, coalesced NCHW float4 stores
        float* oT = (float*)smem;   // [64][132]
#pragma unroll
        for (int mt = 0; mt < 2; mt++)
#pragma unroll
            for (int nt = 0; nt < 4; nt++) {
                int o = n0 + nt * 8 + (lane & 3) * 2;
                int p = m0 + mt * 16 + (lane >> 2);
                oT[o * 132 + p]           = acc[mt][nt][0];
                oT[(o + 1) * 132 + p]     = acc[mt][nt][1];
                oT[o * 132 + p + 8]       = acc[mt][nt][2];
                oT[(o + 1) * 132 + p + 8] = acc[mt][nt][3];
            }
        __syncthreads();
        {
            size_t obase = (size_t)b * OO * HWIMG + ip0;
            for (int i = tid; i < OO * (MT / 4); i += 256) {
                int o = i >> 5, p4 = i & 31;
                float4 v = *(const float4*)(oT + o * 132 + p4 * 4);
                *(float4*)(out + obase + (size_t)o * HWIMG + p4 * 4) = v;
            }
        }
#undef PARAMS
#undef GATHER
#undef WCOPYW
    }
}

// ---------------- launch ----------------
extern "C" void kernel_launch(void* const* d_in, const int* in_sizes, int n_in,
                              void* d_out, int out_size) {
    const float* x     = (const float*)d_in[0];
    const float* w_off = (const float*)d_in[1];
    const float* b_off = (const float*)d_in[2];
    const float* w_dc  = (const float*)d_in[3];
    const float* b_dc  = (const float*)d_in[4];
    float* out = (float*)d_out;

    cudaFuncSetAttribute(k_fused, cudaFuncAttributeMaxDynamicSharedMemorySize, MAIN_SMEM);

    k_prep<<<BB * HH + (OO * CC * KK + 255) / 256, 256>>>(x, w_off, w_dc);
    k_fused<<<NTIL, 256, MAIN_SMEM>>>(b_off, b_dc, out);
}

// round 9
// speedup vs baseline: 1.2457x; 1.1968x over previous
#include <cuda_runtime.h>
#include <cuda_bf16.h>
#include <cstdint>

#define BB 4
#define CC 64
#define HH 96
#define WW 96
#define TT 18
#define KK 9
#define OO 64
#define HWIMG (HH*WW)          // 9216
#define NPIX (BB*HWIMG)        // 36864
#define MT 128                 // pixels per tile
#define NTIL (NPIX/MT)         // 288

// -------- scratch (device globals) --------
__device__ float g_xn[NPIX * CC];                    // NHWC x (fp32, for bilinear)
__device__ uint4 g_xhl[NPIX * 16];                   // packed bf16 {hi 8B, lo 8B} per 4-ch chunk
__device__ float g_offs[NPIX * TT];                  // [pix][18]
__device__ uint4 g_wdc4[(KK * 2 * OO * CC) / 8];     // bf16 swizzled [k][term][o:64][c:64]
__device__ uint4 g_woff4[(KK * 2 * 32 * CC) / 8];    // bf16 swizzled [k][term][o:32][c:64]

// ---------------- helpers ----------------
__device__ __forceinline__ uint32_t smem_u32(const void* p) {
    uint32_t a;
    asm("{ .reg .u64 t; cvta.to.shared.u64 t, %1; cvt.u32.u64 %0, t; }" : "=r"(a) : "l"(p));
    return a;
}
#define SWZ(b) ((b) ^ (((b) >> 3) & 0x70))

__device__ __forceinline__ uint32_t pack_bf16(float a, float b) {
    __nv_bfloat162 t = __floats2bfloat162_rn(a, b);   // .x=a (low half)
    return *(uint32_t*)&t;
}
__device__ __forceinline__ void split2(float s0, float s1, uint32_t& hi, uint32_t& lo) {
    hi = pack_bf16(s0, s1);
    float h0 = __uint_as_float(hi << 16);
    float h1 = __uint_as_float(hi & 0xFFFF0000u);
    lo = pack_bf16(s0 - h0, s1 - h1);
}
#define STS64(a, r0, r1) asm volatile("st.shared.v2.b32 [%0], {%1,%2};" :: "r"(a), "r"(r0), "r"(r1) : "memory")
#define CPA8(d, s, sz) asm volatile("cp.async.ca.shared.global [%0], [%1], 8, %2;" :: "r"(d), "l"(s), "r"(sz) : "memory")
#define CPA16(d, s)    asm volatile("cp.async.ca.shared.global [%0], [%1], 16;" :: "r"(d), "l"(s) : "memory")
#define CPWAITALL()    asm volatile("cp.async.wait_all;" ::: "memory")

__device__ __forceinline__ void ldm4(uint32_t* r, uint32_t addr) {
    asm volatile("ldmatrix.sync.aligned.m8n8.x4.shared.b16 {%0,%1,%2,%3}, [%4];"
                 : "=r"(r[0]), "=r"(r[1]), "=r"(r[2]), "=r"(r[3]) : "r"(addr));
}
__device__ __forceinline__ void mma_bf16(float* c, const uint32_t* a, uint32_t b0, uint32_t b1) {
    asm volatile(
        "mma.sync.aligned.m16n8k16.row.col.f32.bf16.bf16.f32 "
        "{%0,%1,%2,%3}, {%4,%5,%6,%7}, {%8,%9}, {%0,%1,%2,%3};"
        : "+f"(c[0]), "+f"(c[1]), "+f"(c[2]), "+f"(c[3])
        : "r"(a[0]), "r"(a[1]), "r"(a[2]), "r"(a[3]), "r"(b0), "r"(b1));
}

// ---------------- prep: transpose + bf16 split (blocks 0..383) + weight repack (rest) ----------------
__global__ void k_prep(const float* __restrict__ x,
                       const float* __restrict__ w_off, const float* __restrict__ w_dc) {
    if (blockIdx.x < BB * HH) {
        __shared__ float tile[64][97];
        int bh = blockIdx.x;
        int b = bh / HH;
        const float* src = x + ((size_t)b * CC) * HWIMG + (size_t)(bh % HH) * WW;
        for (int i = threadIdx.x; i < CC * WW; i += blockDim.x) {
            int c = i / WW, w = i % WW;
            tile[c][w] = src[(size_t)c * HWIMG + w];
        }
        __syncthreads();
        float* dst = g_xn + (size_t)bh * WW * CC;
        for (int i = threadIdx.x; i < WW * CC; i += blockDim.x) {
            int w = i / CC, c = i % CC;
            dst[i] = tile[c][w];
        }
        // packed bf16 hi/lo planes
        uint4* dsth = g_xhl + (size_t)bh * WW * 16;
        for (int i = threadIdx.x; i < WW * 16; i += blockDim.x) {
            int w = i >> 4, ck = i & 15;
            float c0 = tile[ck * 4 + 0][w], c1 = tile[ck * 4 + 1][w];
            float c2 = tile[ck * 4 + 2][w], c3 = tile[ck * 4 + 3][w];
            uint4 v;
            split2(c0, c1, v.x, v.z);
            split2(c2, c3, v.y, v.w);
            dsth[i] = v;
        }
    } else {
        int i = (blockIdx.x - BB * HH) * 256 + threadIdx.x;
        if (i < OO * CC * KK) {
            int o = i / (CC * KK);
            int r = i % (CC * KK);
            int c = r / KK;
            int k = r % KK;
            float v = w_dc[i];
            __nv_bfloat16 hi = __float2bfloat16(v);
            __nv_bfloat16 lo = __float2bfloat16(v - __bfloat162float(hi));
            uint32_t sw = SWZ((uint32_t)(o * 128 + c * 2));
            __nv_bfloat16* base = (__nv_bfloat16*)g_wdc4;
            base[(size_t)(k * 2 + 0) * 4096 + (sw >> 1)] = hi;
            base[(size_t)(k * 2 + 1) * 4096 + (sw >> 1)] = lo;
        }
        if (i < 32 * CC * KK) {
            int o = i / (CC * KK);
            int r = i % (CC * KK);
            int c = r / KK;
            int k = r % KK;
            float v = (o < TT) ? w_off[(size_t)o * CC * KK + c * KK + k] : 0.f;
            __nv_bfloat16 hi = __float2bfloat16(v);
            __nv_bfloat16 lo = __float2bfloat16(v - __bfloat162float(hi));
            uint32_t sw = SWZ((uint32_t)(o * 128 + c * 2));
            __nv_bfloat16* base = (__nv_bfloat16*)g_woff4;
            base[(size_t)(k * 2 + 0) * 2048 + (sw >> 1)] = hi;
            base[(size_t)(k * 2 + 1) * 2048 + (sw >> 1)] = lo;
        }
    }
}

// ============== fused offset-conv + deformable conv ==============
// smem: A 4x16KB (buf,term) = 65536 | W 2x16KB = 32768 | sP 8KB
#define MAIN_SW   65536
#define MAIN_SP   (MAIN_SW + 32768)
#define MAIN_SMEM (MAIN_SP + 8192)

__global__ void __launch_bounds__(256, 2) k_fused(const float* __restrict__ b_off,
                                                  const float* __restrict__ b_dc,
                                                  float* __restrict__ out) {
    extern __shared__ __align__(1024) char smem[];
    uint32_t sb = smem_u32(smem);
    float* sP = (float*)(smem + MAIN_SP);

    int tid = threadIdx.x;
    int wid = tid >> 5, lane = tid & 31;

    int pix0 = blockIdx.x * MT;
    int b = pix0 / HWIMG, ip0 = pix0 % HWIMG;
    const float* xb = g_xn + (size_t)b * HWIMG * CC;
    const char* xb8 = (const char*)xb;
    const char* xhl8 = (const char*)(g_xhl + (size_t)b * HWIMG * 16);
    int lpx = tid >> 4;      // pixel sub-index within gather pass
    int ck  = tid & 15;      // 16B channel chunk

    int ph = 0, pw = 0;
    if (tid < 128) {
        int ip = ip0 + tid;
        ph = ip / WW; pw = ip - ph * WW;
    }

    // gather swizzle base (XOR applied before adding ps*2048 — safe)
    uint32_t swbase;
    {
        uint32_t chb = (uint32_t)(ck * 8);
        swbase = ((uint32_t)(lpx * 128) + chb) ^ ((uint32_t)(lpx & 7) << 4);
    }
    uint32_t lmask = (uint32_t)(lane & 7) << 4;

    // ===================== PHASE A: offset conv (N=32, 18 real) =====================
    {
        int m0 = wid * 16;
        uint32_t arowo, browo[2], segAo, segBo;
        {
            int rowoffA = ((lane >> 3) & 1) * 8 + (lane & 7);
            segAo = (uint32_t)((lane >> 4) * 16);
            arowo = (uint32_t)((m0 + rowoffA) * 128);
            int rowoffB = ((lane >> 4) & 1) * 8 + (lane & 7);
            segBo = (uint32_t)(((lane >> 3) & 1) * 16);
#pragma unroll
            for (int ntp = 0; ntp < 2; ntp++)
                browo[ntp] = (uint32_t)((ntp * 16 + rowoffB) * 128);
        }

        float acc[3][4];
#pragma unroll
        for (int nt = 0; nt < 3; nt++) {
            int o = nt * 8 + (lane & 3) * 2;
            float b0v = (o < TT) ? b_off[o] : 0.f;
            float b1v = (o + 1 < TT) ? b_off[o + 1] : 0.f;
            acc[nt][0] = b0v; acc[nt][1] = b1v;
            acc[nt][2] = b0v; acc[nt][3] = b1v;
        }

#define POFF(KI, PB) do {                                                          \
        int y = ph + (KI) / 3 - 1, x = pw + (KI) % 3 - 1;                          \
        int sz = ((unsigned)y < HH && (unsigned)x < WW) ? 8 : 0;                   \
        int yc = min(max(y, 0), HH - 1), xc = min(max(x, 0), WW - 1);              \
        int2* p = (int2*)(sP + (PB) * 256) + tid;                                  \
        *p = make_int2(sz, (yc * WW + xc) * 256);                                  \
    } while (0)

#define GATHS(BUF, PB) do {                                                        \
        uint32_t dh = sb + ((BUF) * 2 + 0) * 16384 + swbase;                       \
        uint32_t dl = sb + ((BUF) * 2 + 1) * 16384 + swbase;                       \
        const int2* sPp = (const int2*)(sP + (PB) * 256);                          \
        _Pragma("unroll")                                                          \
        for (int ps = 0; ps < 8; ps++) {                                           \
            int2 pv = sPp[ps * 16 + lpx];                                          \
            const char* srcp = xhl8 + pv.y + ck * 16;                              \
            CPA8(dh + ps * 2048, srcp, pv.x);                                      \
            CPA8(dl + ps * 2048, srcp + 8, pv.x);                                  \
        }                                                                          \
    } while (0)

#define WCOPYO(KI, BUF) do {                                                       \
        const char* srcw = (const char*)(g_woff4 + (size_t)(KI) * 512);            \
        uint32_t dstw = sb + MAIN_SW + (BUF) * 8192;                               \
        for (int i = tid - 128; i < 512; i += 128) CPA16(dstw + i * 16, srcw + i * 16); \
    } while (0)

        if (tid < 128) POFF(0, 0);
        else           WCOPYO(0, 0);
        __syncthreads();
        GATHS(0, 0);
        if (tid < 128) POFF(1, 1);
        CPWAITALL();
        __syncthreads();

#pragma unroll 1
        for (int k = 0; k < KK; k++) {
            int buf = k & 1;
            if (tid < 128) {
                if (k < KK - 2) POFF(k + 2, buf);
            } else {
                if (k < KK - 1) WCOPYO(k + 1, buf ^ 1);
            }
            if (k < KK - 1) GATHS(buf ^ 1, (k + 1) & 1);
            uint32_t abH = sb + (buf * 2 + 0) * 16384;
            uint32_t abL = sb + (buf * 2 + 1) * 16384;
            uint32_t wbH = sb + MAIN_SW + buf * 8192;
            uint32_t wbL = wbH + 4096;
#pragma unroll
            for (int kt = 0; kt < 4; kt++) {
                uint32_t colA = ((uint32_t)(kt * 32) + segAo) ^ lmask;
                uint32_t colB = ((uint32_t)(kt * 32) + segBo) ^ lmask;
                uint32_t aH[4], aL[4], bH[2][4], bL[2][4];
                ldm4(aH, abH + arowo + colA);
                ldm4(aL, abL + arowo + colA);
#pragma unroll
                for (int ntp = 0; ntp < 2; ntp++) {
                    ldm4(bH[ntp], wbH + browo[ntp] + colB);
                    ldm4(bL[ntp], wbL + browo[ntp] + colB);
                }
#pragma unroll
                for (int nt = 0; nt < 3; nt++) {
                    int ntp = nt >> 1, hi2 = (nt & 1) * 2;
                    mma_bf16(acc[nt], aH, bH[ntp][hi2], bH[ntp][hi2 + 1]);
                    mma_bf16(acc[nt], aH, bL[ntp][hi2], bL[ntp][hi2 + 1]);
                    mma_bf16(acc[nt], aL, bH[ntp][hi2], bH[ntp][hi2 + 1]);
                }
            }
            CPWAITALL();
            __syncthreads();
        }

        // epilogue A: oT[p][o] stride 20 -> g_offs[pix][18]
        float* oT = (float*)smem;   // [128][20]
#pragma unroll
        for (int nt = 0; nt < 3; nt++) {
            int o = nt * 8 + (lane & 3) * 2;
            int p = m0 + (lane >> 2);
            if (o < TT) {
                oT[p * 20 + o] = acc[nt][0];
                oT[(p + 8) * 20 + o] = acc[nt][2];
            }
            if (o + 1 < TT) {
                oT[p * 20 + o + 1] = acc[nt][1];
                oT[(p + 8) * 20 + o + 1] = acc[nt][3];
            }
        }
        __syncthreads();
        {
            float* dst = g_offs + (size_t)pix0 * TT;
            for (int i = tid; i < MT * TT; i += 256)
                dst[i] = oT[(i / TT) * 20 + (i % TT)];
        }
#undef POFF
#undef GATHS
#undef WCOPYO
    }
    __syncthreads();   // g_offs visible block-wide; smem free for phase B

    // ===================== PHASE B: main deformable conv (N=64) =====================
    {
        int wm = wid & 3, wn = wid >> 2;
        int m0 = wm * 32, n0 = wn * 32;
        const float* goffp = g_offs;
        if (tid < 128) goffp = g_offs + (size_t)(pix0 + tid) * TT;

        uint32_t arow[2], brow[2], segA, segB;
        {
            int rowoffA = ((lane >> 3) & 1) * 8 + (lane & 7);
            segA = (uint32_t)((lane >> 4) * 16);
#pragma unroll
            for (int mt = 0; mt < 2; mt++)
                arow[mt] = (uint32_t)((m0 + mt * 16 + rowoffA) * 128);
            int rowoffB = ((lane >> 4) & 1) * 8 + (lane & 7);
            segB = (uint32_t)(((lane >> 3) & 1) * 16);
#pragma unroll
            for (int ntp = 0; ntp < 2; ntp++)
                brow[ntp] = (uint32_t)((n0 + ntp * 16 + rowoffB) * 128);
        }

        float acc[2][4][4];
#pragma unroll
        for (int nt = 0; nt < 4; nt++) {
            int o = n0 + nt * 8 + (lane & 3) * 2;
            float b0v = b_dc[o], b1v = b_dc[o + 1];
#pragma unroll
            for (int mt = 0; mt < 2; mt++) {
                acc[mt][nt][0] = b0v; acc[mt][nt][1] = b1v;
                acc[mt][nt][2] = b0v; acc[mt][nt][3] = b1v;
            }
        }

#define PARAMS(KI, PB) do {                                                        \
        float2 dxy = *(const float2*)(goffp + 2 * (KI));                           \
        float py  = (float)(ph + (KI) / 3 - 1) + dxy.x;                            \
        float pxx = (float)(pw + (KI) % 3 - 1) + dxy.y;                            \
        float y0f = floorf(py), x0f = floorf(pxx);                                 \
        float ly = py - y0f, lx = pxx - x0f;                                       \
        int y0 = (int)y0f, x0 = (int)x0f, y1 = y0 + 1, x1 = x0 + 1;                \
        float w00 = (1.f - ly) * (1.f - lx), w01 = (1.f - ly) * lx;                \
        float w10 = ly * (1.f - lx), w11 = ly * lx;                                \
        bool vy0 = (unsigned)y0 < HH, vy1 = (unsigned)y1 < HH;                     \
        bool vx0 = (unsigned)x0 < WW, vx1 = (unsigned)x1 < WW;                     \
        w00 *= (float)(vy0 && vx0); w01 *= (float)(vy0 && vx1);                    \
        w10 *= (float)(vy1 && vx0); w11 *= (float)(vy1 && vx1);                    \
        int yc0 = min(max(y0, 0), HH - 1), yc1 = min(max(y1, 0), HH - 1);          \
        int xc0 = min(max(x0, 0), WW - 1), xc1 = min(max(x1, 0), WW - 1);          \
        float4* p = (float4*)(sP + (PB) * 1024) + tid * 2;                         \
        p[0] = make_float4(w00, w01, w10, w11);                                    \
        p[1] = make_float4(__int_as_float((yc0 * WW + xc0) * (CC * 4)),            \
                           __int_as_float((yc0 * WW + xc1) * (CC * 4)),            \
                           __int_as_float((yc1 * WW + xc0) * (CC * 4)),            \
                           __int_as_float((yc1 * WW + xc1) * (CC * 4)));           \
    } while (0)

// batch of 2 pixels: 8 independent LDG.128 issued before any consumption
#define GATHER(BUF, PB) do {                                                       \
        uint32_t dh = sb + ((BUF) * 2 + 0) * 16384 + swbase;                       \
        uint32_t dl = sb + ((BUF) * 2 + 1) * 16384 + swbase;                       \
        const float4* sPp = (const float4*)(sP + (PB) * 1024);                     \
        _Pragma("unroll")                                                          \
        for (int hb = 0; hb < 4; hb++) {                                           \
            const float4* pp0 = sPp + ((hb * 2 + 0) * 16 + lpx) * 2;               \
            const float4* pp1 = sPp + ((hb * 2 + 1) * 16 + lpx) * 2;               \
            float4 wv0 = pp0[0], iv0 = pp0[1];                                     \
            float4 wv1 = pp1[0], iv1 = pp1[1];                                     \
            float4 a0 = ((const float4*)(xb8 + __float_as_int(iv0.x)))[ck];        \
            float4 b0 = ((const float4*)(xb8 + __float_as_int(iv0.y)))[ck];        \
            float4 c0 = ((const float4*)(xb8 + __float_as_int(iv0.z)))[ck];        \
            float4 d0 = ((const float4*)(xb8 + __float_as_int(iv0.w)))[ck];        \
            float4 a1 = ((const float4*)(xb8 + __float_as_int(iv1.x)))[ck];        \
            float4 b1 = ((const float4*)(xb8 + __float_as_int(iv1.y)))[ck];        \
            float4 c1 = ((const float4*)(xb8 + __float_as_int(iv1.z)))[ck];        \
            float4 d1 = ((const float4*)(xb8 + __float_as_int(iv1.w)))[ck];        \
            {                                                                      \
                float s0 = wv0.x * a0.x + wv0.y * b0.x + wv0.z * c0.x + wv0.w * d0.x; \
                float s1 = wv0.x * a0.y + wv0.y * b0.y + wv0.z * c0.y + wv0.w * d0.y; \
                float s2 = wv0.x * a0.z + wv0.y * b0.z + wv0.z * c0.z + wv0.w * d0.z; \
                float s3 = wv0.x * a0.w + wv0.y * b0.w + wv0.z * c0.w + wv0.w * d0.w; \
                uint32_t hiA, loA, hiB, loB;                                       \
                split2(s0, s1, hiA, loA);                                          \
                split2(s2, s3, hiB, loB);                                          \
                STS64(dh + (hb * 2 + 0) * 2048, hiA, hiB);                         \
                STS64(dl + (hb * 2 + 0) * 2048, loA, loB);                         \
            }                                                                      \
            {                                                                      \
                float s0 = wv1.x * a1.x + wv1.y * b1.x + wv1.z * c1.x + wv1.w * d1.x; \
                float s1 = wv1.x * a1.y + wv1.y * b1.y + wv1.z * c1.y + wv1.w * d1.y; \
                float s2 = wv1.x * a1.z + wv1.y * b1.z + wv1.z * c1.z + wv1.w * d1.z; \
                float s3 = wv1.x * a1.w + wv1.y * b1.w + wv1.z * c1.w + wv1.w * d1.w; \
                uint32_t hiA, loA, hiB, loB;                                       \
                split2(s0, s1, hiA, loA);                                          \
                split2(s2, s3, hiB, loB);                                          \
                STS64(dh + (hb * 2 + 1) * 2048, hiA, hiB);                         \
                STS64(dl + (hb * 2 + 1) * 2048, loA, loB);                         \
            }                                                                      \
        }                                                                          \
    } while (0)

#define WCOPYW(KI, BUF) do {                                                       \
        const char* srcw = (const char*)(g_wdc4 + (size_t)(KI) * 1024);            \
        uint32_t dstw = sb + MAIN_SW + (BUF) * 16384;                              \
        for (int i = tid - 128; i < 1024; i += 128) CPA16(dstw + i * 16, srcw + i * 16); \
    } while (0)

        if (tid < 128) PARAMS(0, 0);
        else           WCOPYW(0, 0);
        __syncthreads();
        GATHER(0, 0);
        if (tid < 128) PARAMS(1, 1);
        CPWAITALL();
        __syncthreads();

#pragma unroll 1
        for (int k = 0; k < KK; k++) {
            int buf = k & 1;
            if (tid < 128) {
                if (k < KK - 2) PARAMS(k + 2, buf);
            } else {
                if (k < KK - 1) WCOPYW(k + 1, buf ^ 1);
            }
            uint32_t abH = sb + (buf * 2 + 0) * 16384;
            uint32_t abL = sb + (buf * 2 + 1) * 16384;
            uint32_t wbH = sb + MAIN_SW + buf * 16384;
            uint32_t wbL = wbH + 8192;
#pragma unroll
            for (int kt = 0; kt < 4; kt++) {
                uint32_t colA = ((uint32_t)(kt * 32) + segA) ^ lmask;
                uint32_t colB = ((uint32_t)(kt * 32) + segB) ^ lmask;
                uint32_t aH[2][4], aL[2][4], bH[2][4], bL[2][4];
#pragma unroll
                for (int mt = 0; mt < 2; mt++) {
                    ldm4(aH[mt], abH + arow[mt] + colA);
                    ldm4(aL[mt], abL + arow[mt] + colA);
                }
#pragma unroll
                for (int ntp = 0; ntp < 2; ntp++) {
                    ldm4(bH[ntp], wbH + brow[ntp] + colB);
                    ldm4(bL[ntp], wbL + brow[ntp] + colB);
                }
#pragma unroll
                for (int mt = 0; mt < 2; mt++)
#pragma unroll
                    for (int nt = 0; nt < 4; nt++) {
                        int ntp = nt >> 1, hi2 = (nt & 1) * 2;
                        mma_bf16(acc[mt][nt], aH[mt], bH[ntp][hi2], bH[ntp][hi2 + 1]);
                        mma_bf16(acc[mt][nt], aH[mt], bL[ntp][hi2], bL[ntp][hi2 + 1]);
                        mma_bf16(acc[mt][nt], aL[mt], bH[ntp][hi2], bH[ntp][hi2 + 1]);
                    }
            }
            if (k < KK - 1) GATHER(buf ^ 1, (k + 1) & 1);
            CPWAITALL();
            __syncthreads();
        }

        // epilogue B: transpose via smem, coalesced NCHW float4 stores
        float* oT = (float*)smem;   // [64][132]
#pragma unroll
        for (int mt = 0; mt < 2; mt++)
#pragma unroll
            for (int nt = 0; nt < 4; nt++) {
                int o = n0 + nt * 8 + (lane & 3) * 2;
                int p = m0 + mt * 16 + (lane >> 2);
                oT[o * 132 + p]           = acc[mt][nt][0];
                oT[(o + 1) * 132 + p]     = acc[mt][nt][1];
                oT[o * 132 + p + 8]       = acc[mt][nt][2];
                oT[(o + 1) * 132 + p + 8] = acc[mt][nt][3];
            }
        __syncthreads();
        {
            size_t obase = (size_t)b * OO * HWIMG + ip0;
            for (int i = tid; i < OO * (MT / 4); i += 256) {
                int o = i >> 5, p4 = i & 31;
                float4 v = *(const float4*)(oT + o * 132 + p4 * 4);
                *(float4*)(out + obase + (size_t)o * HWIMG + p4 * 4) = v;
            }
        }
#undef PARAMS
#undef GATHER
#undef WCOPYW
    }
}

// ---------------- launch ----------------
extern "C" void kernel_launch(void* const* d_in, const int* in_sizes, int n_in,
                              void* d_out, int out_size) {
    const float* x     = (const float*)d_in[0];
    const float* w_off = (const float*)d_in[1];
    const float* b_off = (const float*)d_in[2];
    const float* w_dc  = (const float*)d_in[3];
    const float* b_dc  = (const float*)d_in[4];
    float* out = (float*)d_out;

    cudaFuncSetAttribute(k_fused, cudaFuncAttributeMaxDynamicSharedMemorySize, MAIN_SMEM);

    k_prep<<<BB * HH + (OO * CC * KK + 255) / 256, 256>>>(x, w_off, w_dc);
    k_fused<<<NTIL, 256, MAIN_SMEM>>>(b_off, b_dc, out);
}

// round 10
// speedup vs baseline: 1.2542x; 1.0068x over previous
#include <cuda_runtime.h>
#include <cuda_bf16.h>
#include <cstdint>

#define BB 4
#define CC 64
#define HH 96
#define WW 96
#define TT 18
#define KK 9
#define OO 64
#define HWIMG (HH*WW)          // 9216
#define NPIX (BB*HWIMG)        // 36864
#define MT 128                 // pixels per tile
#define NTIL (NPIX/MT)         // 288

// -------- scratch (device globals) --------
__device__ float g_xn[NPIX * CC];                    // NHWC x (fp32, for bilinear)
__device__ uint4 g_xhl[NPIX * 16];                   // packed bf16 {hi 8B, lo 8B} per 4-ch chunk
__device__ float g_offs[NPIX * TT];                  // [pix][18]
__device__ uint4 g_wdc4[(KK * 2 * OO * CC) / 8];     // bf16 swizzled [k][term][o:64][c:64]
__device__ uint4 g_woff4[(KK * 2 * 32 * CC) / 8];    // bf16 swizzled [k][term][o:32][c:64]

// ---------------- helpers ----------------
__device__ __forceinline__ uint32_t smem_u32(const void* p) {
    uint32_t a;
    asm("{ .reg .u64 t; cvta.to.shared.u64 t, %1; cvt.u32.u64 %0, t; }" : "=r"(a) : "l"(p));
    return a;
}
#define SWZ(b) ((b) ^ (((b) >> 3) & 0x70))

__device__ __forceinline__ uint32_t pack_bf16(float a, float b) {
    __nv_bfloat162 t = __floats2bfloat162_rn(a, b);   // .x=a (low half)
    return *(uint32_t*)&t;
}
__device__ __forceinline__ void split2(float s0, float s1, uint32_t& hi, uint32_t& lo) {
    hi = pack_bf16(s0, s1);
    float h0 = __uint_as_float(hi << 16);
    float h1 = __uint_as_float(hi & 0xFFFF0000u);
    lo = pack_bf16(s0 - h0, s1 - h1);
}
#define STS64(a, r0, r1) asm volatile("st.shared.v2.b32 [%0], {%1,%2};" :: "r"(a), "r"(r0), "r"(r1) : "memory")
#define CPA8(d, s, sz) asm volatile("cp.async.ca.shared.global [%0], [%1], 8, %2;" :: "r"(d), "l"(s), "r"(sz) : "memory")
#define CPA16(d, s)    asm volatile("cp.async.ca.shared.global [%0], [%1], 16;" :: "r"(d), "l"(s) : "memory")
#define CPWAITALL()    asm volatile("cp.async.wait_all;" ::: "memory")

__device__ __forceinline__ void ldm4(uint32_t* r, uint32_t addr) {
    asm volatile("ldmatrix.sync.aligned.m8n8.x4.shared.b16 {%0,%1,%2,%3}, [%4];"
                 : "=r"(r[0]), "=r"(r[1]), "=r"(r[2]), "=r"(r[3]) : "r"(addr));
}
__device__ __forceinline__ void mma_bf16(float* c, const uint32_t* a, uint32_t b0, uint32_t b1) {
    asm volatile(
        "mma.sync.aligned.m16n8k16.row.col.f32.bf16.bf16.f32 "
        "{%0,%1,%2,%3}, {%4,%5,%6,%7}, {%8,%9}, {%0,%1,%2,%3};"
        : "+f"(c[0]), "+f"(c[1]), "+f"(c[2]), "+f"(c[3])
        : "r"(a[0]), "r"(a[1]), "r"(a[2]), "r"(a[3]), "r"(b0), "r"(b1));
}

// ---------------- prep: transpose + bf16 split (blocks 0..383) + weight repack (rest) ----------------
__global__ void k_prep(const float* __restrict__ x,
                       const float* __restrict__ w_off, const float* __restrict__ w_dc) {
    if (blockIdx.x < BB * HH) {
        __shared__ float tile[64][97];
        int bh = blockIdx.x;
        int b = bh / HH;
        const float* src = x + ((size_t)b * CC) * HWIMG + (size_t)(bh % HH) * WW;
        for (int i = threadIdx.x; i < CC * WW; i += blockDim.x) {
            int c = i / WW, w = i % WW;
            tile[c][w] = src[(size_t)c * HWIMG + w];
        }
        __syncthreads();
        float* dst = g_xn + (size_t)bh * WW * CC;
        for (int i = threadIdx.x; i < WW * CC; i += blockDim.x) {
            int w = i / CC, c = i % CC;
            dst[i] = tile[c][w];
        }
        uint4* dsth = g_xhl + (size_t)bh * WW * 16;
        for (int i = threadIdx.x; i < WW * 16; i += blockDim.x) {
            int w = i >> 4, ck = i & 15;
            float c0 = tile[ck * 4 + 0][w], c1 = tile[ck * 4 + 1][w];
            float c2 = tile[ck * 4 + 2][w], c3 = tile[ck * 4 + 3][w];
            uint4 v;
            split2(c0, c1, v.x, v.z);
            split2(c2, c3, v.y, v.w);
            dsth[i] = v;
        }
    } else {
        int i = (blockIdx.x - BB * HH) * 256 + threadIdx.x;
        if (i < OO * CC * KK) {
            int o = i / (CC * KK);
            int r = i % (CC * KK);
            int c = r / KK;
            int k = r % KK;
            float v = w_dc[i];
            __nv_bfloat16 hi = __float2bfloat16(v);
            __nv_bfloat16 lo = __float2bfloat16(v - __bfloat162float(hi));
            uint32_t sw = SWZ((uint32_t)(o * 128 + c * 2));
            __nv_bfloat16* base = (__nv_bfloat16*)g_wdc4;
            base[(size_t)(k * 2 + 0) * 4096 + (sw >> 1)] = hi;
            base[(size_t)(k * 2 + 1) * 4096 + (sw >> 1)] = lo;
        }
        if (i < 32 * CC * KK) {
            int o = i / (CC * KK);
            int r = i % (CC * KK);
            int c = r / KK;
            int k = r % KK;
            float v = (o < TT) ? w_off[(size_t)o * CC * KK + c * KK + k] : 0.f;
            __nv_bfloat16 hi = __float2bfloat16(v);
            __nv_bfloat16 lo = __float2bfloat16(v - __bfloat162float(hi));
            uint32_t sw = SWZ((uint32_t)(o * 128 + c * 2));
            __nv_bfloat16* base = (__nv_bfloat16*)g_woff4;
            base[(size_t)(k * 2 + 0) * 2048 + (sw >> 1)] = hi;
            base[(size_t)(k * 2 + 1) * 2048 + (sw >> 1)] = lo;
        }
    }
}

// ============== fused offset-conv + deformable conv ==============
// smem: A 4x16KB (buf,term) = 65536 | W 2x16KB = 32768 | sP 8KB
#define MAIN_SW   65536
#define MAIN_SP   (MAIN_SW + 32768)
#define MAIN_SMEM (MAIN_SP + 8192)

__global__ void __launch_bounds__(256, 2) k_fused(const float* __restrict__ b_off,
                                                  const float* __restrict__ b_dc,
                                                  float* __restrict__ out) {
    extern __shared__ __align__(1024) char smem[];
    uint32_t sb = smem_u32(smem);
    float* sP = (float*)(smem + MAIN_SP);

    int tid = threadIdx.x;
    int wid = tid >> 5, lane = tid & 31;

    int pix0 = blockIdx.x * MT;
    int b = pix0 / HWIMG, ip0 = pix0 % HWIMG;
    const float* xb = g_xn + (size_t)b * HWIMG * CC;
    const char* xb8 = (const char*)xb;
    const char* xhl8 = (const char*)(g_xhl + (size_t)b * HWIMG * 16);
    int lpx = tid >> 4;      // pixel sub-index within gather pass
    int ck  = tid & 15;      // 16B channel chunk

    int ph = 0, pw = 0;
    if (tid < 128) {
        int ip = ip0 + tid;
        ph = ip / WW; pw = ip - ph * WW;
    }

    uint32_t swbase;
    {
        uint32_t chb = (uint32_t)(ck * 8);
        swbase = ((uint32_t)(lpx * 128) + chb) ^ ((uint32_t)(lpx & 7) << 4);
    }
    uint32_t lmask = (uint32_t)(lane & 7) << 4;

    // ===================== PHASE A: offset conv (N=32, 18 real) =====================
    {
        int m0 = wid * 16;
        uint32_t arowo, browo[2], segAo, segBo;
        {
            int rowoffA = ((lane >> 3) & 1) * 8 + (lane & 7);
            segAo = (uint32_t)((lane >> 4) * 16);
            arowo = (uint32_t)((m0 + rowoffA) * 128);
            int rowoffB = ((lane >> 4) & 1) * 8 + (lane & 7);
            segBo = (uint32_t)(((lane >> 3) & 1) * 16);
#pragma unroll
            for (int ntp = 0; ntp < 2; ntp++)
                browo[ntp] = (uint32_t)((ntp * 16 + rowoffB) * 128);
        }

        float acc[3][4];
#pragma unroll
        for (int nt = 0; nt < 3; nt++) {
            int o = nt * 8 + (lane & 3) * 2;
            float b0v = (o < TT) ? b_off[o] : 0.f;
            float b1v = (o + 1 < TT) ? b_off[o + 1] : 0.f;
            acc[nt][0] = b0v; acc[nt][1] = b1v;
            acc[nt][2] = b0v; acc[nt][3] = b1v;
        }

#define POFF(KI, PB) do {                                                          \
        int y = ph + (KI) / 3 - 1, x = pw + (KI) % 3 - 1;                          \
        int sz = ((unsigned)y < HH && (unsigned)x < WW) ? 8 : 0;                   \
        int yc = min(max(y, 0), HH - 1), xc = min(max(x, 0), WW - 1);              \
        int2* p = (int2*)(sP + (PB) * 256) + tid;                                  \
        *p = make_int2(sz, (yc * WW + xc) * 256);                                  \
    } while (0)

#define GATHS(BUF, PB) do {                                                        \
        uint32_t dh = sb + ((BUF) * 2 + 0) * 16384 + swbase;                       \
        uint32_t dl = sb + ((BUF) * 2 + 1) * 16384 + swbase;                       \
        const int2* sPp = (const int2*)(sP + (PB) * 256);                          \
        _Pragma("unroll")                                                          \
        for (int ps = 0; ps < 8; ps++) {                                           \
            int2 pv = sPp[ps * 16 + lpx];                                          \
            const char* srcp = xhl8 + pv.y + ck * 16;                              \
            CPA8(dh + ps * 2048, srcp, pv.x);                                      \
            CPA8(dl + ps * 2048, srcp + 8, pv.x);                                  \
        }                                                                          \
    } while (0)

#define WCOPYO(KI, BUF) do {                                                       \
        const char* srcw = (const char*)(g_woff4 + (size_t)(KI) * 512);            \
        uint32_t dstw = sb + MAIN_SW + (BUF) * 8192;                               \
        for (int i = tid - 128; i < 512; i += 128) CPA16(dstw + i * 16, srcw + i * 16); \
    } while (0)

        if (tid < 128) POFF(0, 0);
        else           WCOPYO(0, 0);
        __syncthreads();
        GATHS(0, 0);
        if (tid < 128) POFF(1, 1);
        CPWAITALL();
        __syncthreads();

#pragma unroll 1
        for (int k = 0; k < KK; k++) {
            int buf = k & 1;
            if (tid < 128) {
                if (k < KK - 2) POFF(k + 2, buf);
            } else {
                if (k < KK - 1) WCOPYO(k + 1, buf ^ 1);
            }
            if (k < KK - 1) GATHS(buf ^ 1, (k + 1) & 1);
            uint32_t abH = sb + (buf * 2 + 0) * 16384;
            uint32_t abL = sb + (buf * 2 + 1) * 16384;
            uint32_t wbH = sb + MAIN_SW + buf * 8192;
            uint32_t wbL = wbH + 4096;
#pragma unroll
            for (int kt = 0; kt < 4; kt++) {
                uint32_t colA = ((uint32_t)(kt * 32) + segAo) ^ lmask;
                uint32_t colB = ((uint32_t)(kt * 32) + segBo) ^ lmask;
                uint32_t aH[4], aL[4], bH[2][4], bL[2][4];
                ldm4(aH, abH + arowo + colA);
                ldm4(aL, abL + arowo + colA);
#pragma unroll
                for (int ntp = 0; ntp < 2; ntp++) {
                    ldm4(bH[ntp], wbH + browo[ntp] + colB);
                    ldm4(bL[ntp], wbL + browo[ntp] + colB);
                }
#pragma unroll
                for (int nt = 0; nt < 3; nt++) {
                    int ntp = nt >> 1, hi2 = (nt & 1) * 2;
                    mma_bf16(acc[nt], aH, bH[ntp][hi2], bH[ntp][hi2 + 1]);
                    mma_bf16(acc[nt], aH, bL[ntp][hi2], bL[ntp][hi2 + 1]);
                    mma_bf16(acc[nt], aL, bH[ntp][hi2], bH[ntp][hi2 + 1]);
                }
            }
            CPWAITALL();
            __syncthreads();
        }

        // epilogue A: oT[p][o] stride 20 -> g_offs[pix][18]
        float* oT = (float*)smem;   // [128][20]
#pragma unroll
        for (int nt = 0; nt < 3; nt++) {
            int o = nt * 8 + (lane & 3) * 2;
            int p = m0 + (lane >> 2);
            if (o < TT) {
                oT[p * 20 + o] = acc[nt][0];
                oT[(p + 8) * 20 + o] = acc[nt][2];
            }
            if (o + 1 < TT) {
                oT[p * 20 + o + 1] = acc[nt][1];
                oT[(p + 8) * 20 + o + 1] = acc[nt][3];
            }
        }
        __syncthreads();
        {
            float* dst = g_offs + (size_t)pix0 * TT;
            for (int i = tid; i < MT * TT; i += 256)
                dst[i] = oT[(i / TT) * 20 + (i % TT)];
        }
#undef POFF
#undef GATHS
#undef WCOPYO
    }
    __syncthreads();   // g_offs visible block-wide; smem free for phase B

    // ===================== PHASE B: main deformable conv (N=64) =====================
    {
        int wm = wid & 3, wn = wid >> 2;
        int m0 = wm * 32, n0 = wn * 32;
        const float* goffp = g_offs;
        if (tid < 128) goffp = g_offs + (size_t)(pix0 + tid) * TT;

        uint32_t arow[2], brow[2], segA, segB;
        {
            int rowoffA = ((lane >> 3) & 1) * 8 + (lane & 7);
            segA = (uint32_t)((lane >> 4) * 16);
#pragma unroll
            for (int mt = 0; mt < 2; mt++)
                arow[mt] = (uint32_t)((m0 + mt * 16 + rowoffA) * 128);
            int rowoffB = ((lane >> 4) & 1) * 8 + (lane & 7);
            segB = (uint32_t)(((lane >> 3) & 1) * 16);
#pragma unroll
            for (int ntp = 0; ntp < 2; ntp++)
                brow[ntp] = (uint32_t)((n0 + ntp * 16 + rowoffB) * 128);
        }

        float acc[2][4][4];
#pragma unroll
        for (int nt = 0; nt < 4; nt++) {
            int o = n0 + nt * 8 + (lane & 3) * 2;
            float b0v = b_dc[o], b1v = b_dc[o + 1];
#pragma unroll
            for (int mt = 0; mt < 2; mt++) {
                acc[mt][nt][0] = b0v; acc[mt][nt][1] = b1v;
                acc[mt][nt][2] = b0v; acc[mt][nt][3] = b1v;
            }
        }

#define PARAMS(KI, PB) do {                                                        \
        float2 dxy = *(const float2*)(goffp + 2 * (KI));                           \
        float py  = (float)(ph + (KI) / 3 - 1) + dxy.x;                            \
        float pxx = (float)(pw + (KI) % 3 - 1) + dxy.y;                            \
        float y0f = floorf(py), x0f = floorf(pxx);                                 \
        float ly = py - y0f, lx = pxx - x0f;                                       \
        int y0 = (int)y0f, x0 = (int)x0f, y1 = y0 + 1, x1 = x0 + 1;                \
        float w00 = (1.f - ly) * (1.f - lx), w01 = (1.f - ly) * lx;                \
        float w10 = ly * (1.f - lx), w11 = ly * lx;                                \
        bool vy0 = (unsigned)y0 < HH, vy1 = (unsigned)y1 < HH;                     \
        bool vx0 = (unsigned)x0 < WW, vx1 = (unsigned)x1 < WW;                     \
        w00 *= (float)(vy0 && vx0); w01 *= (float)(vy0 && vx1);                    \
        w10 *= (float)(vy1 && vx0); w11 *= (float)(vy1 && vx1);                    \
        int yc0 = min(max(y0, 0), HH - 1), yc1 = min(max(y1, 0), HH - 1);          \
        int xc0 = min(max(x0, 0), WW - 1), xc1 = min(max(x1, 0), WW - 1);          \
        float4* p = (float4*)(sP + (PB) * 1024) + tid * 2;                         \
        p[0] = make_float4(w00, w01, w10, w11);                                    \
        p[1] = make_float4(__int_as_float((yc0 * WW + xc0) * (CC * 4)),            \
                           __int_as_float((yc0 * WW + xc1) * (CC * 4)),            \
                           __int_as_float((yc1 * WW + xc0) * (CC * 4)),            \
                           __int_as_float((yc1 * WW + xc1) * (CC * 4)));           \
    } while (0)

// full gather for preamble (tap 0 only)
#define GATHER0() do {                                                             \
        uint32_t dh = sb + 0 * 16384 + swbase;                                     \
        uint32_t dl = sb + 1 * 16384 + swbase;                                     \
        const float4* sPp = (const float4*)sP;                                     \
        _Pragma("unroll")                                                          \
        for (int ps = 0; ps < 8; ps++) {                                           \
            const float4* pp = sPp + (ps * 16 + lpx) * 2;                          \
            float4 wv = pp[0], iv = pp[1];                                         \
            float4 a4 = ((const float4*)(xb8 + __float_as_int(iv.x)))[ck];         \
            float4 b4 = ((const float4*)(xb8 + __float_as_int(iv.y)))[ck];         \
            float4 c4 = ((const float4*)(xb8 + __float_as_int(iv.z)))[ck];         \
            float4 d4 = ((const float4*)(xb8 + __float_as_int(iv.w)))[ck];         \
            float s0 = wv.x * a4.x + wv.y * b4.x + wv.z * c4.x + wv.w * d4.x;      \
            float s1 = wv.x * a4.y + wv.y * b4.y + wv.z * c4.y + wv.w * d4.y;      \
            float s2 = wv.x * a4.z + wv.y * b4.z + wv.z * c4.z + wv.w * d4.z;      \
            float s3 = wv.x * a4.w + wv.y * b4.w + wv.z * c4.w + wv.w * d4.w;      \
            uint32_t hiA, loA, hiB, loB;                                           \
            split2(s0, s1, hiA, loA);                                              \
            split2(s2, s3, hiB, loB);                                              \
            STS64(dh + ps * 2048, hiA, hiB);                                       \
            STS64(dl + ps * 2048, loA, loB);                                       \
        }                                                                          \
    } while (0)

#define WCOPYW(KI, BUF) do {                                                       \
        const char* srcw = (const char*)(g_wdc4 + (size_t)(KI) * 1024);            \
        uint32_t dstw = sb + MAIN_SW + (BUF) * 16384;                              \
        for (int i = tid - 128; i < 1024; i += 128) CPA16(dstw + i * 16, srcw + i * 16); \
    } while (0)

        if (tid < 128) PARAMS(0, 0);
        else           WCOPYW(0, 0);
        __syncthreads();
        GATHER0();
        if (tid < 128) PARAMS(1, 1);
        CPWAITALL();
        __syncthreads();

#pragma unroll 1
        for (int k = 0; k < KK; k++) {
            int buf = k & 1;
            if (tid < 128) {
                if (k < KK - 2) PARAMS(k + 2, buf);
            } else {
                if (k < KK - 1) WCOPYW(k + 1, buf ^ 1);
            }
            uint32_t abH = sb + (buf * 2 + 0) * 16384;
            uint32_t abL = sb + (buf * 2 + 1) * 16384;
            uint32_t wbH = sb + MAIN_SW + buf * 16384;
            uint32_t wbL = wbH + 8192;
            uint32_t dh = sb + ((buf ^ 1) * 2 + 0) * 16384 + swbase;
            uint32_t dl = sb + ((buf ^ 1) * 2 + 1) * 16384 + swbase;
            const float4* sPp = (const float4*)(sP + ((k + 1) & 1) * 1024);
            bool dog = (k < KK - 1);

            // software-pipelined: per sub-step issue 1 pixel-batch gather, do half-kt mma, consume
            uint32_t bH[2][4], bL[2][4];
#pragma unroll
            for (int sub = 0; sub < 8; sub++) {
                const int kt = sub >> 1, mt = sub & 1;
                float4 ga, gb, gc, gd, wv;
                if (dog) {
                    const float4* pp = sPp + (sub * 16 + lpx) * 2;
                    wv = pp[0];
                    float4 iv = pp[1];
                    ga = ((const float4*)(xb8 + __float_as_int(iv.x)))[ck];
                    gb = ((const float4*)(xb8 + __float_as_int(iv.y)))[ck];
                    gc = ((const float4*)(xb8 + __float_as_int(iv.z)))[ck];
                    gd = ((const float4*)(xb8 + __float_as_int(iv.w)))[ck];
                }
                uint32_t colA = ((uint32_t)(kt * 32) + segA) ^ lmask;
                uint32_t aH[4], aL[4];
                ldm4(aH, abH + arow[mt] + colA);
                ldm4(aL, abL + arow[mt] + colA);
                if (mt == 0) {
                    uint32_t colB = ((uint32_t)(kt * 32) + segB) ^ lmask;
                    ldm4(bH[0], wbH + brow[0] + colB);
                    ldm4(bH[1], wbH + brow[1] + colB);
                    ldm4(bL[0], wbL + brow[0] + colB);
                    ldm4(bL[1], wbL + brow[1] + colB);
                }
#pragma unroll
                for (int nt = 0; nt < 4; nt++) {
                    int ntp = nt >> 1, hi2 = (nt & 1) * 2;
                    mma_bf16(acc[mt][nt], aH, bH[ntp][hi2], bH[ntp][hi2 + 1]);
                    mma_bf16(acc[mt][nt], aH, bL[ntp][hi2], bL[ntp][hi2 + 1]);
                    mma_bf16(acc[mt][nt], aL, bH[ntp][hi2], bH[ntp][hi2 + 1]);
                }
                if (dog) {
                    float s0 = wv.x * ga.x + wv.y * gb.x + wv.z * gc.x + wv.w * gd.x;
                    float s1 = wv.x * ga.y + wv.y * gb.y + wv.z * gc.y + wv.w * gd.y;
                    float s2 = wv.x * ga.z + wv.y * gb.z + wv.z * gc.z + wv.w * gd.z;
                    float s3 = wv.x * ga.w + wv.y * gb.w + wv.z * gc.w + wv.w * gd.w;
                    uint32_t hiA, loA, hiB, loB;
                    split2(s0, s1, hiA, loA);
                    split2(s2, s3, hiB, loB);
                    STS64(dh + sub * 2048, hiA, hiB);
                    STS64(dl + sub * 2048, loA, loB);
                }
            }
            CPWAITALL();
            __syncthreads();
        }

        // epilogue B: transpose via smem, coalesced NCHW float4 stores
        float* oT = (float*)smem;   // [64][132]
#pragma unroll
        for (int mt = 0; mt < 2; mt++)
#pragma unroll
            for (int nt = 0; nt < 4; nt++) {
                int o = n0 + nt * 8 + (lane & 3) * 2;
                int p = m0 + mt * 16 + (lane >> 2);
                oT[o * 132 + p]           = acc[mt][nt][0];
                oT[(o + 1) * 132 + p]     = acc[mt][nt][1];
                oT[o * 132 + p + 8]       = acc[mt][nt][2];
                oT[(o + 1) * 132 + p + 8] = acc[mt][nt][3];
            }
        __syncthreads();
        {
            size_t obase = (size_t)b * OO * HWIMG + ip0;
            for (int i = tid; i < OO * (MT / 4); i += 256) {
                int o = i >> 5, p4 = i & 31;
                float4 v = *(const float4*)(oT + o * 132 + p4 * 4);
                *(float4*)(out + obase + (size_t)o * HWIMG + p4 * 4) = v;
            }
        }
#undef PARAMS
#undef GATHER0
#undef WCOPYW
    }
}

// ---------------- launch ----------------
extern "C" void kernel_launch(void* const* d_in, const int* in_sizes, int n_in,
                              void* d_out, int out_size) {
    const float* x     = (const float*)d_in[0];
    const float* w_off = (const float*)d_in[1];
    const float* b_off = (const float*)d_in[2];
    const float* w_dc  = (const float*)d_in[3];
    const float* b_dc  = (const float*)d_in[4];
    float* out = (float*)d_out;

    cudaFuncSetAttribute(k_fused, cudaFuncAttributeMaxDynamicSharedMemorySize, MAIN_SMEM);

    k_prep<<<BB * HH + (OO * CC * KK + 255) / 256, 256>>>(x, w_off, w_dc);
    k_fused<<<NTIL, 256, MAIN_SMEM>>>(b_off, b_dc, out);
}

// round 12
// speedup vs baseline: 1.3765x; 1.0975x over previous
#include <cuda_runtime.h>
#include <cuda_bf16.h>
#include <cstdint>

#define BB 4
#define CC 64
#define HH 96
#define WW 96
#define TT 18
#define KK 9
#define OO 64
#define HWIMG (HH*WW)          // 9216
#define NPIX (BB*HWIMG)        // 36864
#define MT 128                 // pixels per tile
#define NTIL (NPIX/MT)         // 288

// -------- scratch (device globals) --------
__device__ float g_xn[NPIX * CC];                    // NHWC x (fp32, for bilinear)
__device__ uint4 g_xhl[NPIX * 16];                   // packed bf16 {hi 8B, lo 8B} per 4-ch chunk
__device__ float g_offs[NPIX * TT];                  // [pix][18]
__device__ uint4 g_wdc4[(KK * 2 * OO * CC) / 8];     // bf16 swizzled [k][term][o:64][c:64]
__device__ uint4 g_woff4[(KK * 2 * 32 * CC) / 8];    // bf16 swizzled [k][term][o:32][c:64]

// ---------------- helpers ----------------
__device__ __forceinline__ uint32_t smem_u32(const void* p) {
    uint32_t a;
    asm("{ .reg .u64 t; cvta.to.shared.u64 t, %1; cvt.u32.u64 %0, t; }" : "=r"(a) : "l"(p));
    return a;
}
#define SWZ(b) ((b) ^ (((b) >> 3) & 0x70))

__device__ __forceinline__ uint32_t pack_bf16(float a, float b) {
    __nv_bfloat162 t = __floats2bfloat162_rn(a, b);   // .x=a (low half)
    return *(uint32_t*)&t;
}
__device__ __forceinline__ void split2(float s0, float s1, uint32_t& hi, uint32_t& lo) {
    hi = pack_bf16(s0, s1);
    float h0 = __uint_as_float(hi << 16);
    float h1 = __uint_as_float(hi & 0xFFFF0000u);
    lo = pack_bf16(s0 - h0, s1 - h1);
}
#define STS64(a, r0, r1) asm volatile("st.shared.v2.b32 [%0], {%1,%2};" :: "r"(a), "r"(r0), "r"(r1) : "memory")
#define CPA8(d, s, sz) asm volatile("cp.async.ca.shared.global [%0], [%1], 8, %2;" :: "r"(d), "l"(s), "r"(sz) : "memory")
#define CPA16(d, s)    asm volatile("cp.async.ca.shared.global [%0], [%1], 16;" :: "r"(d), "l"(s) : "memory")
#define CPWAITALL()    asm volatile("cp.async.wait_all;" ::: "memory")

__device__ __forceinline__ void ldm4(uint32_t* r, uint32_t addr) {
    asm volatile("ldmatrix.sync.aligned.m8n8.x4.shared.b16 {%0,%1,%2,%3}, [%4];"
                 : "=r"(r[0]), "=r"(r[1]), "=r"(r[2]), "=r"(r[3]) : "r"(addr));
}
__device__ __forceinline__ void mma_bf16(float* c, const uint32_t* a, uint32_t b0, uint32_t b1) {
    asm volatile(
        "mma.sync.aligned.m16n8k16.row.col.f32.bf16.bf16.f32 "
        "{%0,%1,%2,%3}, {%4,%5,%6,%7}, {%8,%9}, {%0,%1,%2,%3};"
        : "+f"(c[0]), "+f"(c[1]), "+f"(c[2]), "+f"(c[3])
        : "r"(a[0]), "r"(a[1]), "r"(a[2]), "r"(a[3]), "r"(b0), "r"(b1));
}

// ---------------- prep: transpose + bf16 split (blocks 0..383) + weight repack (rest) ----------------
__global__ void k_prep(const float* __restrict__ x,
                       const float* __restrict__ w_off, const float* __restrict__ w_dc) {
    if (blockIdx.x < BB * HH) {
        __shared__ float tile[64][97];
        int bh = blockIdx.x;
        int b = bh / HH;
        const float* src = x + ((size_t)b * CC) * HWIMG + (size_t)(bh % HH) * WW;
        for (int i = threadIdx.x; i < CC * WW; i += blockDim.x) {
            int c = i / WW, w = i % WW;
            tile[c][w] = src[(size_t)c * HWIMG + w];
        }
        __syncthreads();
        float* dst = g_xn + (size_t)bh * WW * CC;
        for (int i = threadIdx.x; i < WW * CC; i += blockDim.x) {
            int w = i / CC, c = i % CC;
            dst[i] = tile[c][w];
        }
        uint4* dsth = g_xhl + (size_t)bh * WW * 16;
        for (int i = threadIdx.x; i < WW * 16; i += blockDim.x) {
            int w = i >> 4, ck = i & 15;
            float c0 = tile[ck * 4 + 0][w], c1 = tile[ck * 4 + 1][w];
            float c2 = tile[ck * 4 + 2][w], c3 = tile[ck * 4 + 3][w];
            uint4 v;
            split2(c0, c1, v.x, v.z);
            split2(c2, c3, v.y, v.w);
            dsth[i] = v;
        }
    } else {
        int i = (blockIdx.x - BB * HH) * 256 + threadIdx.x;
        if (i < OO * CC * KK) {
            int o = i / (CC * KK);
            int r = i % (CC * KK);
            int c = r / KK;
            int k = r % KK;
            float v = w_dc[i];
            __nv_bfloat16 hi = __float2bfloat16(v);
            __nv_bfloat16 lo = __float2bfloat16(v - __bfloat162float(hi));
            uint32_t sw = SWZ((uint32_t)(o * 128 + c * 2));
            __nv_bfloat16* base = (__nv_bfloat16*)g_wdc4;
            base[(size_t)(k * 2 + 0) * 4096 + (sw >> 1)] = hi;
            base[(size_t)(k * 2 + 1) * 4096 + (sw >> 1)] = lo;
        }
        if (i < 32 * CC * KK) {
            int o = i / (CC * KK);
            int r = i % (CC * KK);
            int c = r / KK;
            int k = r % KK;
            float v = (o < TT) ? w_off[(size_t)o * CC * KK + c * KK + k] : 0.f;
            __nv_bfloat16 hi = __float2bfloat16(v);
            __nv_bfloat16 lo = __float2bfloat16(v - __bfloat162float(hi));
            uint32_t sw = SWZ((uint32_t)(o * 128 + c * 2));
            __nv_bfloat16* base = (__nv_bfloat16*)g_woff4;
            base[(size_t)(k * 2 + 0) * 2048 + (sw >> 1)] = hi;
            base[(size_t)(k * 2 + 1) * 2048 + (sw >> 1)] = lo;
        }
    }
}

// ============== fused offset-conv + deformable conv ==============
// smem: A 4x16KB = 65536 | W 2x16KB = 32768 | sP 8KB
#define MAIN_SW   65536
#define MAIN_SP   (MAIN_SW + 32768)
#define MAIN_SMEM (MAIN_SP + 8192)

__global__ void __launch_bounds__(256, 2) k_fused(const float* __restrict__ b_off,
                                                  const float* __restrict__ b_dc,
                                                  float* __restrict__ out) {
    extern __shared__ __align__(1024) char smem[];
    uint32_t sb = smem_u32(smem);
    float* sP = (float*)(smem + MAIN_SP);

    int tid = threadIdx.x;
    int wid = tid >> 5, lane = tid & 31;

    int pix0 = blockIdx.x * MT;
    int b = pix0 / HWIMG, ip0 = pix0 % HWIMG;
    const float* xb = g_xn + (size_t)b * HWIMG * CC;
    const char* xb8 = (const char*)xb;
    const char* xhl8 = (const char*)(g_xhl + (size_t)b * HWIMG * 16);
    int lpx = tid >> 4;      // phase-B gather pixel sub-index
    int ck  = tid & 15;      // phase-B 16B channel chunk

    int ph = 0, pw = 0;
    if (tid < 128) {
        int ip = ip0 + tid;
        ph = ip / WW; pw = ip - ph * WW;
    }

    uint32_t swbase;   // phase-B gather STS base
    {
        uint32_t chb = (uint32_t)(ck * 8);
        swbase = ((uint32_t)(lpx * 128) + chb) ^ ((uint32_t)(lpx & 7) << 4);
    }
    uint32_t lmask = (uint32_t)(lane & 7) << 4;

    // ===================== PHASE A: offset conv (N=24 used of 32) =====================
    // warps 0-3: params + mma (32 rows each). warps 4-7: all cp.async data movement.
    {
        int m0 = wid * 32;   // valid for wid<4
        uint32_t arowA[2], browo[2], segAo, segBo;
        {
            int rowoffA = ((lane >> 3) & 1) * 8 + (lane & 7);
            segAo = (uint32_t)((lane >> 4) * 16);
#pragma unroll
            for (int mt = 0; mt < 2; mt++)
                arowA[mt] = (uint32_t)((m0 + mt * 16 + rowoffA) * 128);
            int rowoffB = ((lane >> 4) & 1) * 8 + (lane & 7);
            segBo = (uint32_t)(((lane >> 3) & 1) * 16);
#pragma unroll
            for (int ntp = 0; ntp < 2; ntp++)
                browo[ntp] = (uint32_t)((ntp * 16 + rowoffB) * 128);
        }
        // data-warp gather addressing: thread t2 = tid-128 covers (lpx2 = t2>>4, ck2 = t2&15)
        int t2 = tid - 128;
        int lpx2 = (t2 >> 4) & 7, ck2 = t2 & 15;
        uint32_t swb2 = ((uint32_t)(lpx2 * 128 + ck2 * 8)) ^ ((uint32_t)lpx2 << 4);

        float acc[2][3][4];
#pragma unroll
        for (int nt = 0; nt < 3; nt++) {
            int o = nt * 8 + (lane & 3) * 2;
            float b0v = (o < TT) ? b_off[o] : 0.f;
            float b1v = (o + 1 < TT) ? b_off[o + 1] : 0.f;
#pragma unroll
            for (int mt = 0; mt < 2; mt++) {
                acc[mt][nt][0] = b0v; acc[mt][nt][1] = b1v;
                acc[mt][nt][2] = b0v; acc[mt][nt][3] = b1v;
            }
        }

#define POFF(KI, PB) do {                                                          \
        int y = ph + (KI) / 3 - 1, x = pw + (KI) % 3 - 1;                          \
        int sz = ((unsigned)y < HH && (unsigned)x < WW) ? 8 : 0;                   \
        int yc = min(max(y, 0), HH - 1), xc = min(max(x, 0), WW - 1);              \
        int2* p = (int2*)(sP + (PB) * 256) + tid;                                  \
        *p = make_int2(sz, (yc * WW + xc) * 256);                                  \
    } while (0)

// hi-only gather by data warps: 16 CPA8 per thread per tap
#define GATHS(BUF, PB) do {                                                        \
        uint32_t dh = sb + (BUF) * 16384 + swb2;                                   \
        const int2* sPp = (const int2*)(sP + (PB) * 256);                          \
        _Pragma("unroll")                                                          \
        for (int ps = 0; ps < 16; ps++) {                                          \
            int2 pv = sPp[ps * 8 + lpx2];                                          \
            const char* srcp = xhl8 + pv.y + ck2 * 16;                             \
            CPA8(dh + ps * 1024, srcp, pv.x);                                      \
        }                                                                          \
    } while (0)

#define WCOPYO(KI, BUF) do {                                                       \
        const char* srcw = (const char*)(g_woff4 + (size_t)(KI) * 512);            \
        uint32_t dstw = sb + MAIN_SW + (BUF) * 8192;                               \
        for (int i = tid - 128; i < 512; i += 128) CPA16(dstw + i * 16, srcw + i * 16); \
    } while (0)

        if (tid < 128) POFF(0, 0);
        else           WCOPYO(0, 0);
        __syncthreads();
        if (tid >= 128) GATHS(0, 0);
        else            POFF(1, 1);
        CPWAITALL();
        __syncthreads();

#pragma unroll 1
        for (int k = 0; k < KK; k++) {
            int buf = k & 1;
            if (tid < 128) {
                if (k < KK - 2) POFF(k + 2, buf);
                // ---- mma (warps 0-3) ----
                uint32_t abH = sb + buf * 16384;
                uint32_t wbH = sb + MAIN_SW + buf * 8192;
                uint32_t wbL = wbH + 4096;
#pragma unroll
                for (int kt = 0; kt < 4; kt++) {
                    uint32_t colA = ((uint32_t)(kt * 32) + segAo) ^ lmask;
                    uint32_t colB = ((uint32_t)(kt * 32) + segBo) ^ lmask;
                    uint32_t bH[2][4], bL[2][4];
#pragma unroll
                    for (int ntp = 0; ntp < 2; ntp++) {
                        ldm4(bH[ntp], wbH + browo[ntp] + colB);
                        ldm4(bL[ntp], wbL + browo[ntp] + colB);
                    }
#pragma unroll
                    for (int mt = 0; mt < 2; mt++) {
                        uint32_t aH[4];
                        ldm4(aH, abH + arowA[mt] + colA);
#pragma unroll
                        for (int nt = 0; nt < 3; nt++) {
                            int ntp = nt >> 1, hi2 = (nt & 1) * 2;
                            mma_bf16(acc[mt][nt], aH, bH[ntp][hi2], bH[ntp][hi2 + 1]);
                            mma_bf16(acc[mt][nt], aH, bL[ntp][hi2], bL[ntp][hi2 + 1]);
                        }
                    }
                }
            } else {
                if (k < KK - 1) {
                    WCOPYO(k + 1, buf ^ 1);
                    GATHS(buf ^ 1, (k + 1) & 1);
                }
            }
            CPWAITALL();
            __syncthreads();
        }

        // epilogue A: oT[p][o] stride 20 -> g_offs[pix][18]  (warps 0-3 hold acc)
        float* oT = (float*)smem;   // [128][20]
        if (tid < 128) {
#pragma unroll
            for (int mt = 0; mt < 2; mt++)
#pragma unroll
                for (int nt = 0; nt < 3; nt++) {
                    int o = nt * 8 + (lane & 3) * 2;
                    int p = m0 + mt * 16 + (lane >> 2);
                    if (o < TT) {
                        oT[p * 20 + o] = acc[mt][nt][0];
                        oT[(p + 8) * 20 + o] = acc[mt][nt][2];
                    }
                    if (o + 1 < TT) {
                        oT[p * 20 + o + 1] = acc[mt][nt][1];
                        oT[(p + 8) * 20 + o + 1] = acc[mt][nt][3];
                    }
                }
        }
        __syncthreads();
        {
            float* dst = g_offs + (size_t)pix0 * TT;
            for (int i = tid; i < MT * TT; i += 256)
                dst[i] = oT[(i / TT) * 20 + (i % TT)];
        }
#undef POFF
#undef GATHS
#undef WCOPYO
    }
    __syncthreads();   // g_offs visible block-wide; smem free for phase B

    // ===================== PHASE B: main deformable conv (N=64) =====================
    {
        int wm = wid & 3, wn = wid >> 2;
        int m0 = wm * 32, n0 = wn * 32;
        const float* goffp = g_offs;
        if (tid < 128) goffp = g_offs + (size_t)(pix0 + tid) * TT;

        uint32_t arow[2], brow[2], segA, segB;
        {
            int rowoffA = ((lane >> 3) & 1) * 8 + (lane & 7);
            segA = (uint32_t)((lane >> 4) * 16);
#pragma unroll
            for (int mt = 0; mt < 2; mt++)
                arow[mt] = (uint32_t)((m0 + mt * 16 + rowoffA) * 128);
            int rowoffB = ((lane >> 4) & 1) * 8 + (lane & 7);
            segB = (uint32_t)(((lane >> 3) & 1) * 16);
#pragma unroll
            for (int ntp = 0; ntp < 2; ntp++)
                brow[ntp] = (uint32_t)((n0 + ntp * 16 + rowoffB) * 128);
        }

        float acc[2][4][4];
#pragma unroll
        for (int nt = 0; nt < 4; nt++) {
            int o = n0 + nt * 8 + (lane & 3) * 2;
            float b0v = b_dc[o], b1v = b_dc[o + 1];
#pragma unroll
            for (int mt = 0; mt < 2; mt++) {
                acc[mt][nt][0] = b0v; acc[mt][nt][1] = b1v;
                acc[mt][nt][2] = b0v; acc[mt][nt][3] = b1v;
            }
        }

#define PARAMS(KI, PB) do {                                                        \
        float2 dxy = *(const float2*)(goffp + 2 * (KI));                           \
        float py  = (float)(ph + (KI) / 3 - 1) + dxy.x;                            \
        float pxx = (float)(pw + (KI) % 3 - 1) + dxy.y;                            \
        float y0f = floorf(py), x0f = floorf(pxx);                                 \
        float ly = py - y0f, lx = pxx - x0f;                                       \
        int y0 = (int)y0f, x0 = (int)x0f, y1 = y0 + 1, x1 = x0 + 1;                \
        float w00 = (1.f - ly) * (1.f - lx), w01 = (1.f - ly) * lx;                \
        float w10 = ly * (1.f - lx), w11 = ly * lx;                                \
        bool vy0 = (unsigned)y0 < HH, vy1 = (unsigned)y1 < HH;                     \
        bool vx0 = (unsigned)x0 < WW, vx1 = (unsigned)x1 < WW;                     \
        w00 *= (float)(vy0 && vx0); w01 *= (float)(vy0 && vx1);                    \
        w10 *= (float)(vy1 && vx0); w11 *= (float)(vy1 && vx1);                    \
        int yc0 = min(max(y0, 0), HH - 1), yc1 = min(max(y1, 0), HH - 1);          \
        int xc0 = min(max(x0, 0), WW - 1), xc1 = min(max(x1, 0), WW - 1);          \
        float4* p = (float4*)(sP + (PB) * 1024) + tid * 2;                         \
        p[0] = make_float4(w00, w01, w10, w11);                                    \
        p[1] = make_float4(__int_as_float((yc0 * WW + xc0) * (CC * 4)),            \
                           __int_as_float((yc0 * WW + xc1) * (CC * 4)),            \
                           __int_as_float((yc1 * WW + xc0) * (CC * 4)),            \
                           __int_as_float((yc1 * WW + xc1) * (CC * 4)));           \
    } while (0)

#define GATHER0() do {                                                             \
        uint32_t dh = sb + 0 * 16384 + swbase;                                     \
        uint32_t dl = sb + 1 * 16384 + swbase;                                     \
        const float4* sPp = (const float4*)sP;                                     \
        _Pragma("unroll")                                                          \
        for (int ps = 0; ps < 8; ps++) {                                           \
            const float4* pp = sPp + (ps * 16 + lpx) * 2;                          \
            float4 wv = pp[0], iv = pp[1];                                         \
            float4 a4 = ((const float4*)(xb8 + __float_as_int(iv.x)))[ck];         \
            float4 b4 = ((const float4*)(xb8 + __float_as_int(iv.y)))[ck];         \
            float4 c4 = ((const float4*)(xb8 + __float_as_int(iv.z)))[ck];         \
            float4 d4 = ((const float4*)(xb8 + __float_as_int(iv.w)))[ck];         \
            float s0 = wv.x * a4.x + wv.y * b4.x + wv.z * c4.x + wv.w * d4.x;      \
            float s1 = wv.x * a4.y + wv.y * b4.y + wv.z * c4.y + wv.w * d4.y;      \
            float s2 = wv.x * a4.z + wv.y * b4.z + wv.z * c4.z + wv.w * d4.z;      \
            float s3 = wv.x * a4.w + wv.y * b4.w + wv.z * c4.w + wv.w * d4.w;      \
            uint32_t hiA, loA, hiB, loB;                                           \
            split2(s0, s1, hiA, loA);                                              \
            split2(s2, s3, hiB, loB);                                              \
            STS64(dh + ps * 2048, hiA, hiB);                                       \
            STS64(dl + ps * 2048, loA, loB);                                       \
        }                                                                          \
    } while (0)

#define WCOPYW(KI, BUF) do {                                                       \
        const char* srcw = (const char*)(g_wdc4 + (size_t)(KI) * 1024);            \
        uint32_t dstw = sb + MAIN_SW + (BUF) * 16384;                              \
        for (int i = tid - 128; i < 1024; i += 128) CPA16(dstw + i * 16, srcw + i * 16); \
    } while (0)

        if (tid < 128) PARAMS(0, 0);
        else           WCOPYW(0, 0);
        __syncthreads();
        GATHER0();
        if (tid < 128) PARAMS(1, 1);
        CPWAITALL();
        __syncthreads();

#pragma unroll 1
        for (int k = 0; k < KK; k++) {
            int buf = k & 1;
            if (tid < 128) {
                if (k < KK - 2) PARAMS(k + 2, buf);
            } else {
                if (k < KK - 1) WCOPYW(k + 1, buf ^ 1);
            }
            uint32_t abH = sb + (buf * 2 + 0) * 16384;
            uint32_t abL = sb + (buf * 2 + 1) * 16384;
            uint32_t wbH = sb + MAIN_SW + buf * 16384;
            uint32_t wbL = wbH + 8192;
            uint32_t dh = sb + ((buf ^ 1) * 2 + 0) * 16384 + swbase;
            uint32_t dl = sb + ((buf ^ 1) * 2 + 1) * 16384 + swbase;
            const float4* sPp = (const float4*)(sP + ((k + 1) & 1) * 1024);
            bool dog = (k < KK - 1);

            uint32_t bH[2][4], bL[2][4];
#pragma unroll
            for (int sub = 0; sub < 8; sub++) {
                const int kt = sub >> 1, mt = sub & 1;
                float4 ga, gb, gc, gd, wv;
                if (dog) {
                    const float4* pp = sPp + (sub * 16 + lpx) * 2;
                    wv = pp[0];
                    float4 iv = pp[1];
                    ga = ((const float4*)(xb8 + __float_as_int(iv.x)))[ck];
                    gb = ((const float4*)(xb8 + __float_as_int(iv.y)))[ck];
                    gc = ((const float4*)(xb8 + __float_as_int(iv.z)))[ck];
                    gd = ((const float4*)(xb8 + __float_as_int(iv.w)))[ck];
                }
                uint32_t colA = ((uint32_t)(kt * 32) + segA) ^ lmask;
                uint32_t aH[4], aL[4];
                ldm4(aH, abH + arow[mt] + colA);
                ldm4(aL, abL + arow[mt] + colA);
                if (mt == 0) {
                    uint32_t colB = ((uint32_t)(kt * 32) + segB) ^ lmask;
                    ldm4(bH[0], wbH + brow[0] + colB);
                    ldm4(bH[1], wbH + brow[1] + colB);
                    ldm4(bL[0], wbL + brow[0] + colB);
                    ldm4(bL[1], wbL + brow[1] + colB);
                }
#pragma unroll
                for (int nt = 0; nt < 4; nt++) {
                    int ntp = nt >> 1, hi2 = (nt & 1) * 2;
                    mma_bf16(acc[mt][nt], aH, bH[ntp][hi2], bH[ntp][hi2 + 1]);
                    mma_bf16(acc[mt][nt], aH, bL[ntp][hi2], bL[ntp][hi2 + 1]);
                    mma_bf16(acc[mt][nt], aL, bH[ntp][hi2], bH[ntp][hi2 + 1]);
                }
                if (dog) {
                    float s0 = wv.x * ga.x + wv.y * gb.x + wv.z * gc.x + wv.w * gd.x;
                    float s1 = wv.x * ga.y + wv.y * gb.y + wv.z * gc.y + wv.w * gd.y;
                    float s2 = wv.x * ga.z + wv.y * gb.z + wv.z * gc.z + wv.w * gd.z;
                    float s3 = wv.x * ga.w + wv.y * gb.w + wv.z * gc.w + wv.w * gd.w;
                    uint32_t hiA, loA, hiB, loB;
                    split2(s0, s1, hiA, loA);
                    split2(s2, s3, hiB, loB);
                    STS64(dh + sub * 2048, hiA, hiB);
                    STS64(dl + sub * 2048, loA, loB);
                }
            }
            CPWAITALL();
            __syncthreads();
        }

        // epilogue B: transpose via smem, coalesced NCHW float4 stores
        float* oT = (float*)smem;   // [64][132]
#pragma unroll
        for (int mt = 0; mt < 2; mt++)
#pragma unroll
            for (int nt = 0; nt < 4; nt++) {
                int o = n0 + nt * 8 + (lane & 3) * 2;
                int p = m0 + mt * 16 + (lane >> 2);
                oT[o * 132 + p]           = acc[mt][nt][0];
                oT[(o + 1) * 132 + p]     = acc[mt][nt][1];
                oT[o * 132 + p + 8]       = acc[mt][nt][2];
                oT[(o + 1) * 132 + p + 8] = acc[mt][nt][3];
            }
        __syncthreads();
        {
            size_t obase = (size_t)b * OO * HWIMG + ip0;
            for (int i = tid; i < OO * (MT / 4); i += 256) {
                int o = i >> 5, p4 = i & 31;
                float4 v = *(const float4*)(oT + o * 132 + p4 * 4);
                *(float4*)(out + obase + (size_t)o * HWIMG + p4 * 4) = v;
            }
        }
#undef PARAMS
#undef GATHER0
#undef WCOPYW
    }
}

// ---------------- launch ----------------
extern "C" void kernel_launch(void* const* d_in, const int* in_sizes, int n_in,
                              void* d_out, int out_size) {
    const float* x     = (const float*)d_in[0];
    const float* w_off = (const float*)d_in[1];
    const float* b_off = (const float*)d_in[2];
    const float* w_dc  = (const float*)d_in[3];
    const float* b_dc  = (const float*)d_in[4];
    float* out = (float*)d_out;

    cudaFuncSetAttribute(k_fused, cudaFuncAttributeMaxDynamicSharedMemorySize, MAIN_SMEM);

    k_prep<<<BB * HH + (OO * CC * KK + 255) / 256, 256>>>(x, w_off, w_dc);
    k_fused<<<NTIL, 256, MAIN_SMEM>>>(b_off, b_dc, out);
}

// round 13
// speedup vs baseline: 1.4301x; 1.0390x over previous
#include <cuda_runtime.h>
#include <cuda_bf16.h>
#include <cuda_fp16.h>
#include <cstdint>

#define BB 4
#define CC 64
#define HH 96
#define WW 96
#define TT 18
#define KK 9
#define OO 64
#define HWIMG (HH*WW)          // 9216
#define NPIX (BB*HWIMG)        // 36864
#define MT 128                 // pixels per tile
#define NTIL (NPIX/MT)         // 288

// -------- scratch (device globals) --------
__device__ float g_xn[NPIX * CC];                    // NHWC x (fp32, for bilinear)
__device__ uint4 g_xhl[NPIX * 16];                   // packed bf16 {hi 8B, lo 8B} per 4-ch chunk
__device__ uint2 g_xh16[NPIX * 16];                  // packed fp16, 8B per 4-ch chunk (phase A)
__device__ float g_offs[NPIX * TT];                  // [pix][18]
__device__ uint4 g_wdc4[(KK * 2 * OO * CC) / 8];     // bf16 swizzled [k][term][o:64][c:64]
__device__ uint4 g_woff16[(KK * 32 * CC * 2) / 16];  // fp16 swizzled [k][o:32][c:64]

// ---------------- helpers ----------------
__device__ __forceinline__ uint32_t smem_u32(const void* p) {
    uint32_t a;
    asm("{ .reg .u64 t; cvta.to.shared.u64 t, %1; cvt.u32.u64 %0, t; }" : "=r"(a) : "l"(p));
    return a;
}
#define SWZ(b) ((b) ^ (((b) >> 3) & 0x70))

__device__ __forceinline__ uint32_t pack_bf16(float a, float b) {
    __nv_bfloat162 t = __floats2bfloat162_rn(a, b);   // .x=a (low half)
    return *(uint32_t*)&t;
}
__device__ __forceinline__ void split2(float s0, float s1, uint32_t& hi, uint32_t& lo) {
    hi = pack_bf16(s0, s1);
    float h0 = __uint_as_float(hi << 16);
    float h1 = __uint_as_float(hi & 0xFFFF0000u);
    lo = pack_bf16(s0 - h0, s1 - h1);
}
#define STS64(a, r0, r1) asm volatile("st.shared.v2.b32 [%0], {%1,%2};" :: "r"(a), "r"(r0), "r"(r1) : "memory")
#define CPA8(d, s, sz) asm volatile("cp.async.ca.shared.global [%0], [%1], 8, %2;" :: "r"(d), "l"(s), "r"(sz) : "memory")
#define CPA16(d, s)    asm volatile("cp.async.ca.shared.global [%0], [%1], 16;" :: "r"(d), "l"(s) : "memory")
#define CPWAITALL()    asm volatile("cp.async.wait_all;" ::: "memory")

__device__ __forceinline__ void ldm4(uint32_t* r, uint32_t addr) {
    asm volatile("ldmatrix.sync.aligned.m8n8.x4.shared.b16 {%0,%1,%2,%3}, [%4];"
                 : "=r"(r[0]), "=r"(r[1]), "=r"(r[2]), "=r"(r[3]) : "r"(addr));
}
__device__ __forceinline__ void mma_bf16(float* c, const uint32_t* a, uint32_t b0, uint32_t b1) {
    asm volatile(
        "mma.sync.aligned.m16n8k16.row.col.f32.bf16.bf16.f32 "
        "{%0,%1,%2,%3}, {%4,%5,%6,%7}, {%8,%9}, {%0,%1,%2,%3};"
        : "+f"(c[0]), "+f"(c[1]), "+f"(c[2]), "+f"(c[3])
        : "r"(a[0]), "r"(a[1]), "r"(a[2]), "r"(a[3]), "r"(b0), "r"(b1));
}
__device__ __forceinline__ void mma_f16(float* c, const uint32_t* a, uint32_t b0, uint32_t b1) {
    asm volatile(
        "mma.sync.aligned.m16n8k16.row.col.f32.f16.f16.f32 "
        "{%0,%1,%2,%3}, {%4,%5,%6,%7}, {%8,%9}, {%0,%1,%2,%3};"
        : "+f"(c[0]), "+f"(c[1]), "+f"(c[2]), "+f"(c[3])
        : "r"(a[0]), "r"(a[1]), "r"(a[2]), "r"(a[3]), "r"(b0), "r"(b1));
}

// ---------------- prep: transpose + packing (blocks 0..383) + weight repack (rest) ----------------
__global__ void k_prep(const float* __restrict__ x,
                       const float* __restrict__ w_off, const float* __restrict__ w_dc) {
    if (blockIdx.x < BB * HH) {
        __shared__ float tile[64][97];
        int bh = blockIdx.x;
        int b = bh / HH;
        const float* src = x + ((size_t)b * CC) * HWIMG + (size_t)(bh % HH) * WW;
        for (int i = threadIdx.x; i < CC * WW; i += blockDim.x) {
            int c = i / WW, w = i % WW;
            tile[c][w] = src[(size_t)c * HWIMG + w];
        }
        __syncthreads();
        float* dst = g_xn + (size_t)bh * WW * CC;
        for (int i = threadIdx.x; i < WW * CC; i += blockDim.x) {
            int w = i / CC, c = i % CC;
            dst[i] = tile[c][w];
        }
        uint4* dsth = g_xhl + (size_t)bh * WW * 16;
        uint2* dst16 = g_xh16 + (size_t)bh * WW * 16;
        for (int i = threadIdx.x; i < WW * 16; i += blockDim.x) {
            int w = i >> 4, ck = i & 15;
            float c0 = tile[ck * 4 + 0][w], c1 = tile[ck * 4 + 1][w];
            float c2 = tile[ck * 4 + 2][w], c3 = tile[ck * 4 + 3][w];
            uint4 v;
            split2(c0, c1, v.x, v.z);
            split2(c2, c3, v.y, v.w);
            dsth[i] = v;
            __half2 h01 = __floats2half2_rn(c0, c1);
            __half2 h23 = __floats2half2_rn(c2, c3);
            dst16[i] = make_uint2(*(uint32_t*)&h01, *(uint32_t*)&h23);
        }
    } else {
        int i = (blockIdx.x - BB * HH) * 256 + threadIdx.x;
        if (i < OO * CC * KK) {
            int o = i / (CC * KK);
            int r = i % (CC * KK);
            int c = r / KK;
            int k = r % KK;
            float v = w_dc[i];
            __nv_bfloat16 hi = __float2bfloat16(v);
            __nv_bfloat16 lo = __float2bfloat16(v - __bfloat162float(hi));
            uint32_t sw = SWZ((uint32_t)(o * 128 + c * 2));
            __nv_bfloat16* base = (__nv_bfloat16*)g_wdc4;
            base[(size_t)(k * 2 + 0) * 4096 + (sw >> 1)] = hi;
            base[(size_t)(k * 2 + 1) * 4096 + (sw >> 1)] = lo;
        }
        if (i < 32 * CC * KK) {
            int o = i / (CC * KK);
            int r = i % (CC * KK);
            int c = r / KK;
            int k = r % KK;
            float v = (o < TT) ? w_off[(size_t)o * CC * KK + c * KK + k] : 0.f;
            uint32_t sw = SWZ((uint32_t)(o * 128 + c * 2));
            __half* base = (__half*)g_woff16;
            base[(size_t)k * 2048 + (sw >> 1)] = __float2half(v);
        }
    }
}

// ============== fused offset-conv + deformable conv ==============
// smem: A 4x16KB = 65536 | W 2x16KB = 32768 | sP 8KB
#define MAIN_SW   65536
#define MAIN_SP   (MAIN_SW + 32768)
#define MAIN_SMEM (MAIN_SP + 8192)

__global__ void __launch_bounds__(256, 2) k_fused(const float* __restrict__ b_off,
                                                  const float* __restrict__ b_dc,
                                                  float* __restrict__ out) {
    extern __shared__ __align__(1024) char smem[];
    uint32_t sb = smem_u32(smem);
    float* sP = (float*)(smem + MAIN_SP);

    int tid = threadIdx.x;
    int wid = tid >> 5, lane = tid & 31;

    int pix0 = blockIdx.x * MT;
    int b = pix0 / HWIMG, ip0 = pix0 % HWIMG;
    const float* xb = g_xn + (size_t)b * HWIMG * CC;
    const char* xb8 = (const char*)xb;
    const char* xh16 = (const char*)(g_xh16 + (size_t)b * HWIMG * 16);
    int lpx = tid >> 4;      // phase-B gather pixel sub-index
    int ck  = tid & 15;      // phase-B 16B channel chunk

    int ph = 0, pw = 0;
    if (tid < 128) {
        int ip = ip0 + tid;
        ph = ip / WW; pw = ip - ph * WW;
    }

    uint32_t swbase;   // phase-B gather STS base
    {
        uint32_t chb = (uint32_t)(ck * 8);
        swbase = ((uint32_t)(lpx * 128) + chb) ^ ((uint32_t)(lpx & 7) << 4);
    }
    uint32_t lmask = (uint32_t)(lane & 7) << 4;

    // ===================== PHASE A: offset conv, fp16 single-term (N=24 used of 32) =====================
    // warps 0-3: params + mma (32 rows each). warps 4-7: all cp.async data movement.
    {
        int m0 = wid * 32;   // valid for wid<4
        uint32_t arowA[2], browo[2], segAo, segBo;
        {
            int rowoffA = ((lane >> 3) & 1) * 8 + (lane & 7);
            segAo = (uint32_t)((lane >> 4) * 16);
#pragma unroll
            for (int mt = 0; mt < 2; mt++)
                arowA[mt] = (uint32_t)((m0 + mt * 16 + rowoffA) * 128);
            int rowoffB = ((lane >> 4) & 1) * 8 + (lane & 7);
            segBo = (uint32_t)(((lane >> 3) & 1) * 16);
#pragma unroll
            for (int ntp = 0; ntp < 2; ntp++)
                browo[ntp] = (uint32_t)((ntp * 16 + rowoffB) * 128);
        }
        // data-warp gather addressing
        int t2 = tid - 128;
        int lpx2 = (t2 >> 4) & 7, ck2 = t2 & 15;
        uint32_t swb2 = ((uint32_t)(lpx2 * 128 + ck2 * 8)) ^ ((uint32_t)lpx2 << 4);

        float acc[2][3][4];
#pragma unroll
        for (int nt = 0; nt < 3; nt++) {
            int o = nt * 8 + (lane & 3) * 2;
            float b0v = (o < TT) ? b_off[o] : 0.f;
            float b1v = (o + 1 < TT) ? b_off[o + 1] : 0.f;
#pragma unroll
            for (int mt = 0; mt < 2; mt++) {
                acc[mt][nt][0] = b0v; acc[mt][nt][1] = b1v;
                acc[mt][nt][2] = b0v; acc[mt][nt][3] = b1v;
            }
        }

#define POFF(KI, PB) do {                                                          \
        int y = ph + (KI) / 3 - 1, x = pw + (KI) % 3 - 1;                          \
        int sz = ((unsigned)y < HH && (unsigned)x < WW) ? 8 : 0;                   \
        int yc = min(max(y, 0), HH - 1), xc = min(max(x, 0), WW - 1);              \
        int2* p = (int2*)(sP + (PB) * 256) + tid;                                  \
        *p = make_int2(sz, (yc * WW + xc) * 128);                                  \
    } while (0)

// fp16 gather by data warps: 16 CPA8 per thread per tap
#define GATHS(BUF, PB) do {                                                        \
        uint32_t dh = sb + (BUF) * 16384 + swb2;                                   \
        const int2* sPp = (const int2*)(sP + (PB) * 256);                          \
        _Pragma("unroll")                                                          \
        for (int ps = 0; ps < 16; ps++) {                                          \
            int2 pv = sPp[ps * 8 + lpx2];                                          \
            const char* srcp = xh16 + pv.y + ck2 * 8;                              \
            CPA8(dh + ps * 1024, srcp, pv.x);                                      \
        }                                                                          \
    } while (0)

#define WCOPYO(KI, BUF) do {                                                       \
        const char* srcw = (const char*)(g_woff16 + (size_t)(KI) * 256);           \
        uint32_t dstw = sb + MAIN_SW + (BUF) * 4096;                               \
        for (int i = tid - 128; i < 256; i += 128) CPA16(dstw + i * 16, srcw + i * 16); \
    } while (0)

        if (tid < 128) POFF(0, 0);
        else           WCOPYO(0, 0);
        __syncthreads();
        if (tid >= 128) GATHS(0, 0);
        else            POFF(1, 1);
        CPWAITALL();
        __syncthreads();

#pragma unroll 1
        for (int k = 0; k < KK; k++) {
            int buf = k & 1;
            if (tid < 128) {
                if (k < KK - 2) POFF(k + 2, buf);
                // ---- mma (warps 0-3), fp16 single-term ----
                uint32_t abH = sb + buf * 16384;
                uint32_t wbH = sb + MAIN_SW + buf * 4096;
#pragma unroll
                for (int kt = 0; kt < 4; kt++) {
                    uint32_t colA = ((uint32_t)(kt * 32) + segAo) ^ lmask;
                    uint32_t colB = ((uint32_t)(kt * 32) + segBo) ^ lmask;
                    uint32_t bF[2][4];
#pragma unroll
                    for (int ntp = 0; ntp < 2; ntp++)
                        ldm4(bF[ntp], wbH + browo[ntp] + colB);
#pragma unroll
                    for (int mt = 0; mt < 2; mt++) {
                        uint32_t aF[4];
                        ldm4(aF, abH + arowA[mt] + colA);
#pragma unroll
                        for (int nt = 0; nt < 3; nt++) {
                            int ntp = nt >> 1, hi2 = (nt & 1) * 2;
                            mma_f16(acc[mt][nt], aF, bF[ntp][hi2], bF[ntp][hi2 + 1]);
                        }
                    }
                }
            } else {
                if (k < KK - 1) {
                    WCOPYO(k + 1, buf ^ 1);
                    GATHS(buf ^ 1, (k + 1) & 1);
                }
            }
            CPWAITALL();
            __syncthreads();
        }

        // epilogue A: oT[p][o] stride 20 -> g_offs[pix][18]
        float* oT = (float*)smem;   // [128][20]
        if (tid < 128) {
#pragma unroll
            for (int mt = 0; mt < 2; mt++)
#pragma unroll
                for (int nt = 0; nt < 3; nt++) {
                    int o = nt * 8 + (lane & 3) * 2;
                    int p = m0 + mt * 16 + (lane >> 2);
                    if (o < TT) {
                        oT[p * 20 + o] = acc[mt][nt][0];
                        oT[(p + 8) * 20 + o] = acc[mt][nt][2];
                    }
                    if (o + 1 < TT) {
                        oT[p * 20 + o + 1] = acc[mt][nt][1];
                        oT[(p + 8) * 20 + o + 1] = acc[mt][nt][3];
                    }
                }
        }
        __syncthreads();
        {
            float* dst = g_offs + (size_t)pix0 * TT;
            for (int i = tid; i < MT * TT; i += 256)
                dst[i] = oT[(i / TT) * 20 + (i % TT)];
        }
#undef POFF
#undef GATHS
#undef WCOPYO
    }
    __syncthreads();   // g_offs visible block-wide; smem free for phase B

    // ===================== PHASE B: main deformable conv (N=64, bf16 3-term) =====================
    {
        int wm = wid & 3, wn = wid >> 2;
        int m0 = wm * 32, n0 = wn * 32;
        const float* goffp = g_offs;
        if (tid < 128) goffp = g_offs + (size_t)(pix0 + tid) * TT;

        uint32_t arow[2], brow[2], segA, segB;
        {
            int rowoffA = ((lane >> 3) & 1) * 8 + (lane & 7);
            segA = (uint32_t)((lane >> 4) * 16);
#pragma unroll
            for (int mt = 0; mt < 2; mt++)
                arow[mt] = (uint32_t)((m0 + mt * 16 + rowoffA) * 128);
            int rowoffB = ((lane >> 4) & 1) * 8 + (lane & 7);
            segB = (uint32_t)(((lane >> 3) & 1) * 16);
#pragma unroll
            for (int ntp = 0; ntp < 2; ntp++)
                brow[ntp] = (uint32_t)((n0 + ntp * 16 + rowoffB) * 128);
        }

        float acc[2][4][4];
#pragma unroll
        for (int nt = 0; nt < 4; nt++) {
            int o = n0 + nt * 8 + (lane & 3) * 2;
            float b0v = b_dc[o], b1v = b_dc[o + 1];
#pragma unroll
            for (int mt = 0; mt < 2; mt++) {
                acc[mt][nt][0] = b0v; acc[mt][nt][1] = b1v;
                acc[mt][nt][2] = b0v; acc[mt][nt][3] = b1v;
            }
        }

#define PARAMS(KI, PB) do {                                                        \
        float2 dxy = *(const float2*)(goffp + 2 * (KI));                           \
        float py  = (float)(ph + (KI) / 3 - 1) + dxy.x;                            \
        float pxx = (float)(pw + (KI) % 3 - 1) + dxy.y;                            \
        float y0f = floorf(py), x0f = floorf(pxx);                                 \
        float ly = py - y0f, lx = pxx - x0f;                                       \
        int y0 = (int)y0f, x0 = (int)x0f, y1 = y0 + 1, x1 = x0 + 1;                \
        float w00 = (1.f - ly) * (1.f - lx), w01 = (1.f - ly) * lx;                \
        float w10 = ly * (1.f - lx), w11 = ly * lx;                                \
        bool vy0 = (unsigned)y0 < HH, vy1 = (unsigned)y1 < HH;                     \
        bool vx0 = (unsigned)x0 < WW, vx1 = (unsigned)x1 < WW;                     \
        w00 *= (float)(vy0 && vx0); w01 *= (float)(vy0 && vx1);                    \
        w10 *= (float)(vy1 && vx0); w11 *= (float)(vy1 && vx1);                    \
        int yc0 = min(max(y0, 0), HH - 1), yc1 = min(max(y1, 0), HH - 1);          \
        int xc0 = min(max(x0, 0), WW - 1), xc1 = min(max(x1, 0), WW - 1);          \
        float4* p = (float4*)(sP + (PB) * 1024) + tid * 2;                         \
        p[0] = make_float4(w00, w01, w10, w11);                                    \
        p[1] = make_float4(__int_as_float((yc0 * WW + xc0) * (CC * 4)),            \
                           __int_as_float((yc0 * WW + xc1) * (CC * 4)),            \
                           __int_as_float((yc1 * WW + xc0) * (CC * 4)),            \
                           __int_as_float((yc1 * WW + xc1) * (CC * 4)));           \
    } while (0)

#define GATHER0() do {                                                             \
        uint32_t dh = sb + 0 * 16384 + swbase;                                     \
        uint32_t dl = sb + 1 * 16384 + swbase;                                     \
        const float4* sPp = (const float4*)sP;                                     \
        _Pragma("unroll")                                                          \
        for (int ps = 0; ps < 8; ps++) {                                           \
            const float4* pp = sPp + (ps * 16 + lpx) * 2;                          \
            float4 wv = pp[0], iv = pp[1];                                         \
            float4 a4 = ((const float4*)(xb8 + __float_as_int(iv.x)))[ck];         \
            float4 b4 = ((const float4*)(xb8 + __float_as_int(iv.y)))[ck];         \
            float4 c4 = ((const float4*)(xb8 + __float_as_int(iv.z)))[ck];         \
            float4 d4 = ((const float4*)(xb8 + __float_as_int(iv.w)))[ck];         \
            float s0 = wv.x * a4.x + wv.y * b4.x + wv.z * c4.x + wv.w * d4.x;      \
            float s1 = wv.x * a4.y + wv.y * b4.y + wv.z * c4.y + wv.w * d4.y;      \
            float s2 = wv.x * a4.z + wv.y * b4.z + wv.z * c4.z + wv.w * d4.z;      \
            float s3 = wv.x * a4.w + wv.y * b4.w + wv.z * c4.w + wv.w * d4.w;      \
            uint32_t hiA, loA, hiB, loB;                                           \
            split2(s0, s1, hiA, loA);                                              \
            split2(s2, s3, hiB, loB);                                              \
            STS64(dh + ps * 2048, hiA, hiB);                                       \
            STS64(dl + ps * 2048, loA, loB);                                       \
        }                                                                          \
    } while (0)

#define WCOPYW(KI, BUF) do {                                                       \
        const char* srcw = (const char*)(g_wdc4 + (size_t)(KI) * 1024);            \
        uint32_t dstw = sb + MAIN_SW + (BUF) * 16384;                              \
        for (int i = tid - 128; i < 1024; i += 128) CPA16(dstw + i * 16, srcw + i * 16); \
    } while (0)

        if (tid < 128) PARAMS(0, 0);
        else           WCOPYW(0, 0);
        __syncthreads();
        GATHER0();
        if (tid < 128) PARAMS(1, 1);
        CPWAITALL();
        __syncthreads();

#pragma unroll 1
        for (int k = 0; k < KK; k++) {
            int buf = k & 1;
            if (tid < 128) {
                if (k < KK - 2) PARAMS(k + 2, buf);
            } else {
                if (k < KK - 1) WCOPYW(k + 1, buf ^ 1);
            }
            uint32_t abH = sb + (buf * 2 + 0) * 16384;
            uint32_t abL = sb + (buf * 2 + 1) * 16384;
            uint32_t wbH = sb + MAIN_SW + buf * 16384;
            uint32_t wbL = wbH + 8192;
            uint32_t dh = sb + ((buf ^ 1) * 2 + 0) * 16384 + swbase;
            uint32_t dl = sb + ((buf ^ 1) * 2 + 1) * 16384 + swbase;
            const float4* sPp = (const float4*)(sP + ((k + 1) & 1) * 1024);
            bool dog = (k < KK - 1);

            uint32_t bH[2][4], bL[2][4];
#pragma unroll
            for (int sub = 0; sub < 8; sub++) {
                const int kt = sub >> 1, mt = sub & 1;
                float4 ga, gb, gc, gd, wv;
                if (dog) {
                    const float4* pp = sPp + (sub * 16 + lpx) * 2;
                    wv = pp[0];
                    float4 iv = pp[1];
                    ga = ((const float4*)(xb8 + __float_as_int(iv.x)))[ck];
                    gb = ((const float4*)(xb8 + __float_as_int(iv.y)))[ck];
                    gc = ((const float4*)(xb8 + __float_as_int(iv.z)))[ck];
                    gd = ((const float4*)(xb8 + __float_as_int(iv.w)))[ck];
                }
                uint32_t colA = ((uint32_t)(kt * 32) + segA) ^ lmask;
                uint32_t aH[4], aL[4];
                ldm4(aH, abH + arow[mt] + colA);
                ldm4(aL, abL + arow[mt] + colA);
                if (mt == 0) {
                    uint32_t colB = ((uint32_t)(kt * 32) + segB) ^ lmask;
                    ldm4(bH[0], wbH + brow[0] + colB);
                    ldm4(bH[1], wbH + brow[1] + colB);
                    ldm4(bL[0], wbL + brow[0] + colB);
                    ldm4(bL[1], wbL + brow[1] + colB);
                }
#pragma unroll
                for (int nt = 0; nt < 4; nt++) {
                    int ntp = nt >> 1, hi2 = (nt & 1) * 2;
                    mma_bf16(acc[mt][nt], aH, bH[ntp][hi2], bH[ntp][hi2 + 1]);
                    mma_bf16(acc[mt][nt], aH, bL[ntp][hi2], bL[ntp][hi2 + 1]);
                    mma_bf16(acc[mt][nt], aL, bH[ntp][hi2], bH[ntp][hi2 + 1]);
                }
                if (dog) {
                    float s0 = wv.x * ga.x + wv.y * gb.x + wv.z * gc.x + wv.w * gd.x;
                    float s1 = wv.x * ga.y + wv.y * gb.y + wv.z * gc.y + wv.w * gd.y;
                    float s2 = wv.x * ga.z + wv.y * gb.z + wv.z * gc.z + wv.w * gd.z;
                    float s3 = wv.x * ga.w + wv.y * gb.w + wv.z * gc.w + wv.w * gd.w;
                    uint32_t hiA, loA, hiB, loB;
                    split2(s0, s1, hiA, loA);
                    split2(s2, s3, hiB, loB);
                    STS64(dh + sub * 2048, hiA, hiB);
                    STS64(dl + sub * 2048, loA, loB);
                }
            }
            CPWAITALL();
            __syncthreads();
        }

        // epilogue B: transpose via smem, coalesced NCHW float4 stores
        float* oT = (float*)smem;   // [64][132]
#pragma unroll
        for (int mt = 0; mt < 2; mt++)
#pragma unroll
            for (int nt = 0; nt < 4; nt++) {
                int o = n0 + nt * 8 + (lane & 3) * 2;
                int p = m0 + mt * 16 + (lane >> 2);
                oT[o * 132 + p]           = acc[mt][nt][0];
                oT[(o + 1) * 132 + p]     = acc[mt][nt][1];
                oT[o * 132 + p + 8]       = acc[mt][nt][2];
                oT[(o + 1) * 132 + p + 8] = acc[mt][nt][3];
            }
        __syncthreads();
        {
            size_t obase = (size_t)b * OO * HWIMG + ip0;
            for (int i = tid; i < OO * (MT / 4); i += 256) {
                int o = i >> 5, p4 = i & 31;
                float4 v = *(const float4*)(oT + o * 132 + p4 * 4);
                *(float4*)(out + obase + (size_t)o * HWIMG + p4 * 4) = v;
            }
        }
#undef PARAMS
#undef GATHER0
#undef WCOPYW
    }
}

// ---------------- launch ----------------
extern "C" void kernel_launch(void* const* d_in, const int* in_sizes, int n_in,
                              void* d_out, int out_size) {
    const float* x     = (const float*)d_in[0];
    const float* w_off = (const float*)d_in[1];
    const float* b_off = (const float*)d_in[2];
    const float* w_dc  = (const float*)d_in[3];
    const float* b_dc  = (const float*)d_in[4];
    float* out = (float*)d_out;

    cudaFuncSetAttribute(k_fused, cudaFuncAttributeMaxDynamicSharedMemorySize, MAIN_SMEM);

    k_prep<<<BB * HH + (OO * CC * KK + 255) / 256, 256>>>(x, w_off, w_dc);
    k_fused<<<NTIL, 256, MAIN_SMEM>>>(b_off, b_dc, out);
}

// round 14
// speedup vs baseline: 1.6505x; 1.1541x over previous
#include <cuda_runtime.h>
#include <cuda_bf16.h>
#include <cuda_fp16.h>
#include <cstdint>

#define BB 4
#define CC 64
#define HH 96
#define WW 96
#define TT 18
#define KK 9
#define OO 64
#define HWIMG (HH*WW)          // 9216
#define NPIX (BB*HWIMG)        // 36864
#define MT 128                 // pixels per tile
#define NTIL (NPIX/MT)         // 288

// -------- scratch (device globals) --------
__device__ float g_xn[NPIX * CC];                    // NHWC x (fp32, for bilinear)
__device__ uint2 g_xh16[NPIX * 16];                  // packed fp16, 8B per 4-ch chunk (phase A)
__device__ float g_offs[NPIX * TT];                  // [pix][18]
__device__ uint4 g_wdc16[KK * 512];                  // fp16 swizzled [k][o:64][c:64], 8KB/tap
__device__ uint4 g_woff16[KK * 256];                 // fp16 swizzled [k][o:32][c:64], 4KB/tap

// ---------------- helpers ----------------
__device__ __forceinline__ uint32_t smem_u32(const void* p) {
    uint32_t a;
    asm("{ .reg .u64 t; cvta.to.shared.u64 t, %1; cvt.u32.u64 %0, t; }" : "=r"(a) : "l"(p));
    return a;
}
#define SWZ(b) ((b) ^ (((b) >> 3) & 0x70))

__device__ __forceinline__ uint32_t pack_f16(float a, float b) {
    __half2 t = __floats2half2_rn(a, b);
    return *(uint32_t*)&t;
}
#define STS64(a, r0, r1) asm volatile("st.shared.v2.b32 [%0], {%1,%2};" :: "r"(a), "r"(r0), "r"(r1) : "memory")
#define CPA8(d, s, sz) asm volatile("cp.async.ca.shared.global [%0], [%1], 8, %2;" :: "r"(d), "l"(s), "r"(sz) : "memory")
#define CPA16(d, s)    asm volatile("cp.async.ca.shared.global [%0], [%1], 16;" :: "r"(d), "l"(s) : "memory")
#define CPWAITALL()    asm volatile("cp.async.wait_all;" ::: "memory")

__device__ __forceinline__ void ldm4(uint32_t* r, uint32_t addr) {
    asm volatile("ldmatrix.sync.aligned.m8n8.x4.shared.b16 {%0,%1,%2,%3}, [%4];"
                 : "=r"(r[0]), "=r"(r[1]), "=r"(r[2]), "=r"(r[3]) : "r"(addr));
}
__device__ __forceinline__ void mma_f16(float* c, const uint32_t* a, uint32_t b0, uint32_t b1) {
    asm volatile(
        "mma.sync.aligned.m16n8k16.row.col.f32.f16.f16.f32 "
        "{%0,%1,%2,%3}, {%4,%5,%6,%7}, {%8,%9}, {%0,%1,%2,%3};"
        : "+f"(c[0]), "+f"(c[1]), "+f"(c[2]), "+f"(c[3])
        : "r"(a[0]), "r"(a[1]), "r"(a[2]), "r"(a[3]), "r"(b0), "r"(b1));
}

// ---------------- prep: transpose + fp16 pack (blocks 0..383) + weight repack (rest) ----------------
__global__ void k_prep(const float* __restrict__ x,
                       const float* __restrict__ w_off, const float* __restrict__ w_dc) {
    if (blockIdx.x < BB * HH) {
        __shared__ float tile[64][97];
        int bh = blockIdx.x;
        int b = bh / HH;
        const float* src = x + ((size_t)b * CC) * HWIMG + (size_t)(bh % HH) * WW;
        for (int i = threadIdx.x; i < CC * WW; i += blockDim.x) {
            int c = i / WW, w = i % WW;
            tile[c][w] = src[(size_t)c * HWIMG + w];
        }
        __syncthreads();
        float* dst = g_xn + (size_t)bh * WW * CC;
        for (int i = threadIdx.x; i < WW * CC; i += blockDim.x) {
            int w = i / CC, c = i % CC;
            dst[i] = tile[c][w];
        }
        uint2* dst16 = g_xh16 + (size_t)bh * WW * 16;
        for (int i = threadIdx.x; i < WW * 16; i += blockDim.x) {
            int w = i >> 4, ck = i & 15;
            float c0 = tile[ck * 4 + 0][w], c1 = tile[ck * 4 + 1][w];
            float c2 = tile[ck * 4 + 2][w], c3 = tile[ck * 4 + 3][w];
            dst16[i] = make_uint2(pack_f16(c0, c1), pack_f16(c2, c3));
        }
    } else {
        int i = (blockIdx.x - BB * HH) * 256 + threadIdx.x;
        if (i < OO * CC * KK) {
            int o = i / (CC * KK);
            int r = i % (CC * KK);
            int c = r / KK;
            int k = r % KK;
            uint32_t sw = SWZ((uint32_t)(o * 128 + c * 2));
            __half* base = (__half*)g_wdc16;
            base[(size_t)k * 4096 + (sw >> 1)] = __float2half(w_dc[i]);
        }
        if (i < 32 * CC * KK) {
            int o = i / (CC * KK);
            int r = i % (CC * KK);
            int c = r / KK;
            int k = r % KK;
            float v = (o < TT) ? w_off[(size_t)o * CC * KK + c * KK + k] : 0.f;
            uint32_t sw = SWZ((uint32_t)(o * 128 + c * 2));
            __half* base = (__half*)g_woff16;
            base[(size_t)k * 2048 + (sw >> 1)] = __float2half(v);
        }
    }
}

// ============== fused offset-conv + deformable conv (all fp16 single-term) ==============
// smem: A 2x16KB = 32768 | W 2x8KB = 16384 | sP 8KB
#define MAIN_SW   32768
#define MAIN_SP   (MAIN_SW + 16384)
#define MAIN_SMEM (MAIN_SP + 8192)

__global__ void __launch_bounds__(256, 2) k_fused(const float* __restrict__ b_off,
                                                  const float* __restrict__ b_dc,
                                                  float* __restrict__ out) {
    extern __shared__ __align__(1024) char smem[];
    uint32_t sb = smem_u32(smem);
    float* sP = (float*)(smem + MAIN_SP);

    int tid = threadIdx.x;
    int wid = tid >> 5, lane = tid & 31;

    int pix0 = blockIdx.x * MT;
    int b = pix0 / HWIMG, ip0 = pix0 % HWIMG;
    const float* xb = g_xn + (size_t)b * HWIMG * CC;
    const char* xb8 = (const char*)xb;
    const char* xh16 = (const char*)(g_xh16 + (size_t)b * HWIMG * 16);
    int lpx = tid >> 4;      // phase-B gather pixel sub-index
    int ck  = tid & 15;      // phase-B 16B channel chunk

    int ph = 0, pw = 0;
    if (tid < 128) {
        int ip = ip0 + tid;
        ph = ip / WW; pw = ip - ph * WW;
    }

    uint32_t swbase;   // phase-B gather STS base (128B rows of fp16, 8B per chunk)
    {
        uint32_t chb = (uint32_t)(ck * 8);
        swbase = ((uint32_t)(lpx * 128) + chb) ^ ((uint32_t)(lpx & 7) << 4);
    }
    uint32_t lmask = (uint32_t)(lane & 7) << 4;

    // ===================== PHASE A: offset conv, fp16 single-term (N=24 used of 32) =====================
    {
        int m0 = wid * 32;   // valid for wid<4
        uint32_t arowA[2], browo[2], segAo, segBo;
        {
            int rowoffA = ((lane >> 3) & 1) * 8 + (lane & 7);
            segAo = (uint32_t)((lane >> 4) * 16);
#pragma unroll
            for (int mt = 0; mt < 2; mt++)
                arowA[mt] = (uint32_t)((m0 + mt * 16 + rowoffA) * 128);
            int rowoffB = ((lane >> 4) & 1) * 8 + (lane & 7);
            segBo = (uint32_t)(((lane >> 3) & 1) * 16);
#pragma unroll
            for (int ntp = 0; ntp < 2; ntp++)
                browo[ntp] = (uint32_t)((ntp * 16 + rowoffB) * 128);
        }
        int t2 = tid - 128;
        int lpx2 = (t2 >> 4) & 7, ck2 = t2 & 15;
        uint32_t swb2 = ((uint32_t)(lpx2 * 128 + ck2 * 8)) ^ ((uint32_t)lpx2 << 4);

        float acc[2][3][4];
#pragma unroll
        for (int nt = 0; nt < 3; nt++) {
            int o = nt * 8 + (lane & 3) * 2;
            float b0v = (o < TT) ? b_off[o] : 0.f;
            float b1v = (o + 1 < TT) ? b_off[o + 1] : 0.f;
#pragma unroll
            for (int mt = 0; mt < 2; mt++) {
                acc[mt][nt][0] = b0v; acc[mt][nt][1] = b1v;
                acc[mt][nt][2] = b0v; acc[mt][nt][3] = b1v;
            }
        }

#define POFF(KI, PB) do {                                                          \
        int y = ph + (KI) / 3 - 1, x = pw + (KI) % 3 - 1;                          \
        int sz = ((unsigned)y < HH && (unsigned)x < WW) ? 8 : 0;                   \
        int yc = min(max(y, 0), HH - 1), xc = min(max(x, 0), WW - 1);              \
        int2* p = (int2*)(sP + (PB) * 256) + tid;                                  \
        *p = make_int2(sz, (yc * WW + xc) * 128);                                  \
    } while (0)

#define GATHS(BUF, PB) do {                                                        \
        uint32_t dh = sb + (BUF) * 16384 + swb2;                                   \
        const int2* sPp = (const int2*)(sP + (PB) * 256);                          \
        _Pragma("unroll")                                                          \
        for (int ps = 0; ps < 16; ps++) {                                          \
            int2 pv = sPp[ps * 8 + lpx2];                                          \
            const char* srcp = xh16 + pv.y + ck2 * 8;                              \
            CPA8(dh + ps * 1024, srcp, pv.x);                                      \
        }                                                                          \
    } while (0)

#define WCOPYO(KI, BUF) do {                                                       \
        const char* srcw = (const char*)(g_woff16 + (size_t)(KI) * 256);           \
        uint32_t dstw = sb + MAIN_SW + (BUF) * 4096;                               \
        for (int i = tid - 128; i < 256; i += 128) CPA16(dstw + i * 16, srcw + i * 16); \
    } while (0)

        if (tid < 128) POFF(0, 0);
        else           WCOPYO(0, 0);
        __syncthreads();
        if (tid >= 128) GATHS(0, 0);
        else            POFF(1, 1);
        CPWAITALL();
        __syncthreads();

#pragma unroll 1
        for (int k = 0; k < KK; k++) {
            int buf = k & 1;
            if (tid < 128) {
                if (k < KK - 2) POFF(k + 2, buf);
                uint32_t abF = sb + buf * 16384;
                uint32_t wbF = sb + MAIN_SW + buf * 4096;
#pragma unroll
                for (int kt = 0; kt < 4; kt++) {
                    uint32_t colA = ((uint32_t)(kt * 32) + segAo) ^ lmask;
                    uint32_t colB = ((uint32_t)(kt * 32) + segBo) ^ lmask;
                    uint32_t bF[2][4];
#pragma unroll
                    for (int ntp = 0; ntp < 2; ntp++)
                        ldm4(bF[ntp], wbF + browo[ntp] + colB);
#pragma unroll
                    for (int mt = 0; mt < 2; mt++) {
                        uint32_t aF[4];
                        ldm4(aF, abF + arowA[mt] + colA);
#pragma unroll
                        for (int nt = 0; nt < 3; nt++) {
                            int ntp = nt >> 1, hi2 = (nt & 1) * 2;
                            mma_f16(acc[mt][nt], aF, bF[ntp][hi2], bF[ntp][hi2 + 1]);
                        }
                    }
                }
            } else {
                if (k < KK - 1) {
                    WCOPYO(k + 1, buf ^ 1);
                    GATHS(buf ^ 1, (k + 1) & 1);
                }
            }
            CPWAITALL();
            __syncthreads();
        }

        // epilogue A: oT[p][o] stride 20 -> g_offs[pix][18]
        float* oT = (float*)smem;   // [128][20]
        if (tid < 128) {
#pragma unroll
            for (int mt = 0; mt < 2; mt++)
#pragma unroll
                for (int nt = 0; nt < 3; nt++) {
                    int o = nt * 8 + (lane & 3) * 2;
                    int p = m0 + mt * 16 + (lane >> 2);
                    if (o < TT) {
                        oT[p * 20 + o] = acc[mt][nt][0];
                        oT[(p + 8) * 20 + o] = acc[mt][nt][2];
                    }
                    if (o + 1 < TT) {
                        oT[p * 20 + o + 1] = acc[mt][nt][1];
                        oT[(p + 8) * 20 + o + 1] = acc[mt][nt][3];
                    }
                }
        }
        __syncthreads();
        {
            float* dst = g_offs + (size_t)pix0 * TT;
            for (int i = tid; i < MT * TT; i += 256)
                dst[i] = oT[(i / TT) * 20 + (i % TT)];
        }
#undef POFF
#undef GATHS
#undef WCOPYO
    }
    __syncthreads();   // g_offs visible block-wide; smem free for phase B

    // ===================== PHASE B: main deformable conv, fp16 single-term (N=64) =====================
    {
        int wm = wid & 3, wn = wid >> 2;
        int m0 = wm * 32, n0 = wn * 32;
        const float* goffp = g_offs;
        if (tid < 128) goffp = g_offs + (size_t)(pix0 + tid) * TT;

        uint32_t arow[2], brow[2], segA, segB;
        {
            int rowoffA = ((lane >> 3) & 1) * 8 + (lane & 7);
            segA = (uint32_t)((lane >> 4) * 16);
#pragma unroll
            for (int mt = 0; mt < 2; mt++)
                arow[mt] = (uint32_t)((m0 + mt * 16 + rowoffA) * 128);
            int rowoffB = ((lane >> 4) & 1) * 8 + (lane & 7);
            segB = (uint32_t)(((lane >> 3) & 1) * 16);
#pragma unroll
            for (int ntp = 0; ntp < 2; ntp++)
                brow[ntp] = (uint32_t)((n0 + ntp * 16 + rowoffB) * 128);
        }

        float acc[2][4][4];
#pragma unroll
        for (int nt = 0; nt < 4; nt++) {
            int o = n0 + nt * 8 + (lane & 3) * 2;
            float b0v = b_dc[o], b1v = b_dc[o + 1];
#pragma unroll
            for (int mt = 0; mt < 2; mt++) {
                acc[mt][nt][0] = b0v; acc[mt][nt][1] = b1v;
                acc[mt][nt][2] = b0v; acc[mt][nt][3] = b1v;
            }
        }

#define PARAMS(KI, PB) do {                                                        \
        float2 dxy = *(const float2*)(goffp + 2 * (KI));                           \
        float py  = (float)(ph + (KI) / 3 - 1) + dxy.x;                            \
        float pxx = (float)(pw + (KI) % 3 - 1) + dxy.y;                            \
        float y0f = floorf(py), x0f = floorf(pxx);                                 \
        float ly = py - y0f, lx = pxx - x0f;                                       \
        int y0 = (int)y0f, x0 = (int)x0f, y1 = y0 + 1, x1 = x0 + 1;                \
        float w00 = (1.f - ly) * (1.f - lx), w01 = (1.f - ly) * lx;                \
        float w10 = ly * (1.f - lx), w11 = ly * lx;                                \
        bool vy0 = (unsigned)y0 < HH, vy1 = (unsigned)y1 < HH;                     \
        bool vx0 = (unsigned)x0 < WW, vx1 = (unsigned)x1 < WW;                     \
        w00 *= (float)(vy0 && vx0); w01 *= (float)(vy0 && vx1);                    \
        w10 *= (float)(vy1 && vx0); w11 *= (float)(vy1 && vx1);                    \
        int yc0 = min(max(y0, 0), HH - 1), yc1 = min(max(y1, 0), HH - 1);          \
        int xc0 = min(max(x0, 0), WW - 1), xc1 = min(max(x1, 0), WW - 1);          \
        float4* p = (float4*)(sP + (PB) * 1024) + tid * 2;                         \
        p[0] = make_float4(w00, w01, w10, w11);                                    \
        p[1] = make_float4(__int_as_float((yc0 * WW + xc0) * (CC * 4)),            \
                           __int_as_float((yc0 * WW + xc1) * (CC * 4)),            \
                           __int_as_float((yc1 * WW + xc0) * (CC * 4)),            \
                           __int_as_float((yc1 * WW + xc1) * (CC * 4)));           \
    } while (0)

#define GATHER0() do {                                                             \
        uint32_t dh = sb + swbase;                                                 \
        const float4* sPp = (const float4*)sP;                                     \
        _Pragma("unroll")                                                          \
        for (int ps = 0; ps < 8; ps++) {                                           \
            const float4* pp = sPp + (ps * 16 + lpx) * 2;                          \
            float4 wv = pp[0], iv = pp[1];                                         \
            float4 a4 = ((const float4*)(xb8 + __float_as_int(iv.x)))[ck];         \
            float4 b4 = ((const float4*)(xb8 + __float_as_int(iv.y)))[ck];         \
            float4 c4 = ((const float4*)(xb8 + __float_as_int(iv.z)))[ck];         \
            float4 d4 = ((const float4*)(xb8 + __float_as_int(iv.w)))[ck];         \
            float s0 = wv.x * a4.x + wv.y * b4.x + wv.z * c4.x + wv.w * d4.x;      \
            float s1 = wv.x * a4.y + wv.y * b4.y + wv.z * c4.y + wv.w * d4.y;      \
            float s2 = wv.x * a4.z + wv.y * b4.z + wv.z * c4.z + wv.w * d4.z;      \
            float s3 = wv.x * a4.w + wv.y * b4.w + wv.z * c4.w + wv.w * d4.w;      \
            STS64(dh + ps * 2048, pack_f16(s0, s1), pack_f16(s2, s3));             \
        }                                                                          \
    } while (0)

#define WCOPYW(KI, BUF) do {                                                       \
        const char* srcw = (const char*)(g_wdc16 + (size_t)(KI) * 512);            \
        uint32_t dstw = sb + MAIN_SW + (BUF) * 8192;                               \
        for (int i = tid - 128; i < 512; i += 128) CPA16(dstw + i * 16, srcw + i * 16); \
    } while (0)

        if (tid < 128) PARAMS(0, 0);
        else           WCOPYW(0, 0);
        __syncthreads();
        GATHER0();
        if (tid < 128) PARAMS(1, 1);
        CPWAITALL();
        __syncthreads();

#pragma unroll 1
        for (int k = 0; k < KK; k++) {
            int buf = k & 1;
            if (tid < 128) {
                if (k < KK - 2) PARAMS(k + 2, buf);
            } else {
                if (k < KK - 1) WCOPYW(k + 1, buf ^ 1);
            }
            uint32_t abF = sb + buf * 16384;
            uint32_t wbF = sb + MAIN_SW + buf * 8192;
            uint32_t dh = sb + (buf ^ 1) * 16384 + swbase;
            const float4* sPp = (const float4*)(sP + ((k + 1) & 1) * 1024);
            bool dog = (k < KK - 1);

            uint32_t bF[2][4];
#pragma unroll
            for (int sub = 0; sub < 8; sub++) {
                const int kt = sub >> 1, mt = sub & 1;
                float4 ga, gb, gc, gd, wv;
                if (dog) {
                    const float4* pp = sPp + (sub * 16 + lpx) * 2;
                    wv = pp[0];
                    float4 iv = pp[1];
                    ga = ((const float4*)(xb8 + __float_as_int(iv.x)))[ck];
                    gb = ((const float4*)(xb8 + __float_as_int(iv.y)))[ck];
                    gc = ((const float4*)(xb8 + __float_as_int(iv.z)))[ck];
                    gd = ((const float4*)(xb8 + __float_as_int(iv.w)))[ck];
                }
                uint32_t colA = ((uint32_t)(kt * 32) + segA) ^ lmask;
                uint32_t aF[4];
                ldm4(aF, abF + arow[mt] + colA);
                if (mt == 0) {
                    uint32_t colB = ((uint32_t)(kt * 32) + segB) ^ lmask;
                    ldm4(bF[0], wbF + brow[0] + colB);
                    ldm4(bF[1], wbF + brow[1] + colB);
                }
#pragma unroll
                for (int nt = 0; nt < 4; nt++) {
                    int ntp = nt >> 1, hi2 = (nt & 1) * 2;
                    mma_f16(acc[mt][nt], aF, bF[ntp][hi2], bF[ntp][hi2 + 1]);
                }
                if (dog) {
                    float s0 = wv.x * ga.x + wv.y * gb.x + wv.z * gc.x + wv.w * gd.x;
                    float s1 = wv.x * ga.y + wv.y * gb.y + wv.z * gc.y + wv.w * gd.y;
                    float s2 = wv.x * ga.z + wv.y * gb.z + wv.z * gc.z + wv.w * gd.z;
                    float s3 = wv.x * ga.w + wv.y * gb.w + wv.z * gc.w + wv.w * gd.w;
                    STS64(dh + sub * 2048, pack_f16(s0, s1), pack_f16(s2, s3));
                }
            }
            CPWAITALL();
            __syncthreads();
        }

        // epilogue B: transpose via smem, coalesced NCHW float4 stores
        float* oT = (float*)smem;   // [64][132]
#pragma unroll
        for (int mt = 0; mt < 2; mt++)
#pragma unroll
            for (int nt = 0; nt < 4; nt++) {
                int o = n0 + nt * 8 + (lane & 3) * 2;
                int p = m0 + mt * 16 + (lane >> 2);
                oT[o * 132 + p]           = acc[mt][nt][0];
                oT[(o + 1) * 132 + p]     = acc[mt][nt][1];
                oT[o * 132 + p + 8]       = acc[mt][nt][2];
                oT[(o + 1) * 132 + p + 8] = acc[mt][nt][3];
            }
        __syncthreads();
        {
            size_t obase = (size_t)b * OO * HWIMG + ip0;
            for (int i = tid; i < OO * (MT / 4); i += 256) {
                int o = i >> 5, p4 = i & 31;
                float4 v = *(const float4*)(oT + o * 132 + p4 * 4);
                *(float4*)(out + obase + (size_t)o * HWIMG + p4 * 4) = v;
            }
        }
#undef PARAMS
#undef GATHER0
#undef WCOPYW
    }
}

// ---------------- launch ----------------
extern "C" void kernel_launch(void* const* d_in, const int* in_sizes, int n_in,
                              void* d_out, int out_size) {
    const float* x     = (const float*)d_in[0];
    const float* w_off = (const float*)d_in[1];
    const float* b_off = (const float*)d_in[2];
    const float* w_dc  = (const float*)d_in[3];
    const float* b_dc  = (const float*)d_in[4];
    float* out = (float*)d_out;

    cudaFuncSetAttribute(k_fused, cudaFuncAttributeMaxDynamicSharedMemorySize, MAIN_SMEM);

    k_prep<<<BB * HH + (OO * CC * KK + 255) / 256, 256>>>(x, w_off, w_dc);
    k_fused<<<NTIL, 256, MAIN_SMEM>>>(b_off, b_dc, out);
}

// round 15
// speedup vs baseline: 1.9539x; 1.1838x over previous
#include <cuda_runtime.h>
#include <cuda_bf16.h>
#include <cuda_fp16.h>
#include <cstdint>

#define BB 4
#define CC 64
#define HH 96
#define WW 96
#define TT 18
#define KK 9
#define OO 64
#define HWIMG (HH*WW)          // 9216
#define NPIX (BB*HWIMG)        // 36864
#define MT 128                 // pixels per tile
#define NTIL (NPIX/MT)         // 288

// -------- scratch (device globals) --------
__device__ uint2 g_xh16[NPIX * 16];                  // packed fp16, 8B per 4-ch chunk
__device__ float g_offs[NPIX * TT];                  // [pix][18]
__device__ uint4 g_wdc16[KK * 512];                  // fp16 swizzled [k][o:64][c:64], 8KB/tap
__device__ uint4 g_woff16[KK * 256];                 // fp16 swizzled [k][o:32][c:64], 4KB/tap

// ---------------- helpers ----------------
__device__ __forceinline__ uint32_t smem_u32(const void* p) {
    uint32_t a;
    asm("{ .reg .u64 t; cvta.to.shared.u64 t, %1; cvt.u32.u64 %0, t; }" : "=r"(a) : "l"(p));
    return a;
}
#define SWZ(b) ((b) ^ (((b) >> 3) & 0x70))

__device__ __forceinline__ uint32_t pack_f16(float a, float b) {
    __half2 t = __floats2half2_rn(a, b);
    return *(uint32_t*)&t;
}
__device__ __forceinline__ uint32_t splat_h2(float a) {
    __half2 t = __float2half2_rn(a);
    return *(uint32_t*)&t;
}
__device__ __forceinline__ __half2 u2h(uint32_t v) { return *(__half2*)&v; }
__device__ __forceinline__ uint32_t h2u(__half2 v) { return *(uint32_t*)&v; }

#define STS64(a, r0, r1) asm volatile("st.shared.v2.b32 [%0], {%1,%2};" :: "r"(a), "r"(r0), "r"(r1) : "memory")
#define CPA8(d, s, sz) asm volatile("cp.async.ca.shared.global [%0], [%1], 8, %2;" :: "r"(d), "l"(s), "r"(sz) : "memory")
#define CPA16(d, s)    asm volatile("cp.async.ca.shared.global [%0], [%1], 16;" :: "r"(d), "l"(s) : "memory")
#define CPWAITALL()    asm volatile("cp.async.wait_all;" ::: "memory")

__device__ __forceinline__ void ldm4(uint32_t* r, uint32_t addr) {
    asm volatile("ldmatrix.sync.aligned.m8n8.x4.shared.b16 {%0,%1,%2,%3}, [%4];"
                 : "=r"(r[0]), "=r"(r[1]), "=r"(r[2]), "=r"(r[3]) : "r"(addr));
}
__device__ __forceinline__ void mma_f16(float* c, const uint32_t* a, uint32_t b0, uint32_t b1) {
    asm volatile(
        "mma.sync.aligned.m16n8k16.row.col.f32.f16.f16.f32 "
        "{%0,%1,%2,%3}, {%4,%5,%6,%7}, {%8,%9}, {%0,%1,%2,%3};"
        : "+f"(c[0]), "+f"(c[1]), "+f"(c[2]), "+f"(c[3])
        : "r"(a[0]), "r"(a[1]), "r"(a[2]), "r"(a[3]), "r"(b0), "r"(b1));
}

// ---------------- prep: transpose + fp16 pack (blocks 0..383) + weight repack (rest) ----------------
__global__ void k_prep(const float* __restrict__ x,
                       const float* __restrict__ w_off, const float* __restrict__ w_dc) {
    if (blockIdx.x < BB * HH) {
        __shared__ float tile[64][97];
        int bh = blockIdx.x;
        int b = bh / HH;
        const float* src = x + ((size_t)b * CC) * HWIMG + (size_t)(bh % HH) * WW;
        for (int i = threadIdx.x; i < CC * WW; i += blockDim.x) {
            int c = i / WW, w = i % WW;
            tile[c][w] = src[(size_t)c * HWIMG + w];
        }
        __syncthreads();
        uint2* dst16 = g_xh16 + (size_t)bh * WW * 16;
        for (int i = threadIdx.x; i < WW * 16; i += blockDim.x) {
            int w = i >> 4, ck = i & 15;
            float c0 = tile[ck * 4 + 0][w], c1 = tile[ck * 4 + 1][w];
            float c2 = tile[ck * 4 + 2][w], c3 = tile[ck * 4 + 3][w];
            dst16[i] = make_uint2(pack_f16(c0, c1), pack_f16(c2, c3));
        }
    } else {
        int i = (blockIdx.x - BB * HH) * 256 + threadIdx.x;
        if (i < OO * CC * KK) {
            int o = i / (CC * KK);
            int r = i % (CC * KK);
            int c = r / KK;
            int k = r % KK;
            uint32_t sw = SWZ((uint32_t)(o * 128 + c * 2));
            __half* base = (__half*)g_wdc16;
            base[(size_t)k * 4096 + (sw >> 1)] = __float2half(w_dc[i]);
        }
        if (i < 32 * CC * KK) {
            int o = i / (CC * KK);
            int r = i % (CC * KK);
            int c = r / KK;
            int k = r % KK;
            float v = (o < TT) ? w_off[(size_t)o * CC * KK + c * KK + k] : 0.f;
            uint32_t sw = SWZ((uint32_t)(o * 128 + c * 2));
            __half* base = (__half*)g_woff16;
            base[(size_t)k * 2048 + (sw >> 1)] = __float2half(v);
        }
    }
}

// ============== fused offset-conv + deformable conv (all fp16) ==============
// smem: A 2x16KB = 32768 | W 2x8KB = 16384 | sP 8KB
#define MAIN_SW   32768
#define MAIN_SP   (MAIN_SW + 16384)
#define MAIN_SMEM (MAIN_SP + 8192)

__global__ void __launch_bounds__(256, 2) k_fused(const float* __restrict__ b_off,
                                                  const float* __restrict__ b_dc,
                                                  float* __restrict__ out) {
    extern __shared__ __align__(1024) char smem[];
    uint32_t sb = smem_u32(smem);
    float* sP = (float*)(smem + MAIN_SP);

    int tid = threadIdx.x;
    int wid = tid >> 5, lane = tid & 31;

    int pix0 = blockIdx.x * MT;
    int b = pix0 / HWIMG, ip0 = pix0 % HWIMG;
    const char* xh16 = (const char*)(g_xh16 + (size_t)b * HWIMG * 16);
    int lpx = tid >> 4;      // phase-B gather pixel sub-index
    int ck  = tid & 15;      // channel chunk (4 fp16 ch = 8B)

    int ph = 0, pw = 0;
    if (tid < 128) {
        int ip = ip0 + tid;
        ph = ip / WW; pw = ip - ph * WW;
    }

    uint32_t swbase;   // gather STS base (128B fp16 rows, 8B per chunk)
    {
        uint32_t chb = (uint32_t)(ck * 8);
        swbase = ((uint32_t)(lpx * 128) + chb) ^ ((uint32_t)(lpx & 7) << 4);
    }
    uint32_t lmask = (uint32_t)(lane & 7) << 4;

    // ===================== PHASE A: offset conv, fp16 (N=24 used of 32) =====================
    {
        int m0 = wid * 32;   // valid for wid<4
        uint32_t arowA[2], browo[2], segAo, segBo;
        {
            int rowoffA = ((lane >> 3) & 1) * 8 + (lane & 7);
            segAo = (uint32_t)((lane >> 4) * 16);
#pragma unroll
            for (int mt = 0; mt < 2; mt++)
                arowA[mt] = (uint32_t)((m0 + mt * 16 + rowoffA) * 128);
            int rowoffB = ((lane >> 4) & 1) * 8 + (lane & 7);
            segBo = (uint32_t)(((lane >> 3) & 1) * 16);
#pragma unroll
            for (int ntp = 0; ntp < 2; ntp++)
                browo[ntp] = (uint32_t)((ntp * 16 + rowoffB) * 128);
        }
        int t2 = tid - 128;
        int lpx2 = (t2 >> 4) & 7, ck2 = t2 & 15;
        uint32_t swb2 = ((uint32_t)(lpx2 * 128 + ck2 * 8)) ^ ((uint32_t)lpx2 << 4);

        float acc[2][3][4];
#pragma unroll
        for (int nt = 0; nt < 3; nt++) {
            int o = nt * 8 + (lane & 3) * 2;
            float b0v = (o < TT) ? b_off[o] : 0.f;
            float b1v = (o + 1 < TT) ? b_off[o + 1] : 0.f;
#pragma unroll
            for (int mt = 0; mt < 2; mt++) {
                acc[mt][nt][0] = b0v; acc[mt][nt][1] = b1v;
                acc[mt][nt][2] = b0v; acc[mt][nt][3] = b1v;
            }
        }

#define POFF(KI, PB) do {                                                          \
        int y = ph + (KI) / 3 - 1, x = pw + (KI) % 3 - 1;                          \
        int sz = ((unsigned)y < HH && (unsigned)x < WW) ? 8 : 0;                   \
        int yc = min(max(y, 0), HH - 1), xc = min(max(x, 0), WW - 1);              \
        int2* p = (int2*)(sP + (PB) * 256) + tid;                                  \
        *p = make_int2(sz, (yc * WW + xc) * 128);                                  \
    } while (0)

#define GATHS(BUF, PB) do {                                                        \
        uint32_t dh = sb + (BUF) * 16384 + swb2;                                   \
        const int2* sPp = (const int2*)(sP + (PB) * 256);                          \
        _Pragma("unroll")                                                          \
        for (int ps = 0; ps < 16; ps++) {                                          \
            int2 pv = sPp[ps * 8 + lpx2];                                          \
            const char* srcp = xh16 + pv.y + ck2 * 8;                              \
            CPA8(dh + ps * 1024, srcp, pv.x);                                      \
        }                                                                          \
    } while (0)

#define WCOPYO(KI, BUF) do {                                                       \
        const char* srcw = (const char*)(g_woff16 + (size_t)(KI) * 256);           \
        uint32_t dstw = sb + MAIN_SW + (BUF) * 4096;                               \
        for (int i = tid - 128; i < 256; i += 128) CPA16(dstw + i * 16, srcw + i * 16); \
    } while (0)

        if (tid < 128) POFF(0, 0);
        else           WCOPYO(0, 0);
        __syncthreads();
        if (tid >= 128) GATHS(0, 0);
        else            POFF(1, 1);
        CPWAITALL();
        __syncthreads();

#pragma unroll 1
        for (int k = 0; k < KK; k++) {
            int buf = k & 1;
            if (tid < 128) {
                if (k < KK - 2) POFF(k + 2, buf);
                uint32_t abF = sb + buf * 16384;
                uint32_t wbF = sb + MAIN_SW + buf * 4096;
#pragma unroll
                for (int kt = 0; kt < 4; kt++) {
                    uint32_t colA = ((uint32_t)(kt * 32) + segAo) ^ lmask;
                    uint32_t colB = ((uint32_t)(kt * 32) + segBo) ^ lmask;
                    uint32_t bF[2][4];
#pragma unroll
                    for (int ntp = 0; ntp < 2; ntp++)
                        ldm4(bF[ntp], wbF + browo[ntp] + colB);
#pragma unroll
                    for (int mt = 0; mt < 2; mt++) {
                        uint32_t aF[4];
                        ldm4(aF, abF + arowA[mt] + colA);
#pragma unroll
                        for (int nt = 0; nt < 3; nt++) {
                            int ntp = nt >> 1, hi2 = (nt & 1) * 2;
                            mma_f16(acc[mt][nt], aF, bF[ntp][hi2], bF[ntp][hi2 + 1]);
                        }
                    }
                }
            } else {
                if (k < KK - 1) {
                    WCOPYO(k + 1, buf ^ 1);
                    GATHS(buf ^ 1, (k + 1) & 1);
                }
            }
            CPWAITALL();
            __syncthreads();
        }

        // epilogue A: oT[p][o] stride 20 -> g_offs[pix][18]
        float* oT = (float*)smem;   // [128][20]
        if (tid < 128) {
#pragma unroll
            for (int mt = 0; mt < 2; mt++)
#pragma unroll
                for (int nt = 0; nt < 3; nt++) {
                    int o = nt * 8 + (lane & 3) * 2;
                    int p = m0 + mt * 16 + (lane >> 2);
                    if (o < TT) {
                        oT[p * 20 + o] = acc[mt][nt][0];
                        oT[(p + 8) * 20 + o] = acc[mt][nt][2];
                    }
                    if (o + 1 < TT) {
                        oT[p * 20 + o + 1] = acc[mt][nt][1];
                        oT[(p + 8) * 20 + o + 1] = acc[mt][nt][3];
                    }
                }
        }
        __syncthreads();
        {
            float* dst = g_offs + (size_t)pix0 * TT;
            for (int i = tid; i < MT * TT; i += 256)
                dst[i] = oT[(i / TT) * 20 + (i % TT)];
        }
#undef POFF
#undef GATHS
#undef WCOPYO
    }
    __syncthreads();   // g_offs visible block-wide; smem free for phase B

    // ===================== PHASE B: main deformable conv, fp16 (N=64) =====================
    {
        int wm = wid & 3, wn = wid >> 2;
        int m0 = wm * 32, n0 = wn * 32;
        const float* goffp = g_offs;
        if (tid < 128) goffp = g_offs + (size_t)(pix0 + tid) * TT;

        uint32_t arow[2], brow[2], segA, segB;
        {
            int rowoffA = ((lane >> 3) & 1) * 8 + (lane & 7);
            segA = (uint32_t)((lane >> 4) * 16);
#pragma unroll
            for (int mt = 0; mt < 2; mt++)
                arow[mt] = (uint32_t)((m0 + mt * 16 + rowoffA) * 128);
            int rowoffB = ((lane >> 4) & 1) * 8 + (lane & 7);
            segB = (uint32_t)(((lane >> 3) & 1) * 16);
#pragma unroll
            for (int ntp = 0; ntp < 2; ntp++)
                brow[ntp] = (uint32_t)((n0 + ntp * 16 + rowoffB) * 128);
        }

        float acc[2][4][4];
#pragma unroll
        for (int nt = 0; nt < 4; nt++) {
            int o = n0 + nt * 8 + (lane & 3) * 2;
            float b0v = b_dc[o], b1v = b_dc[o + 1];
#pragma unroll
            for (int mt = 0; mt < 2; mt++) {
                acc[mt][nt][0] = b0v; acc[mt][nt][1] = b1v;
                acc[mt][nt][2] = b0v; acc[mt][nt][3] = b1v;
            }
        }

// PARAMS: store half2-splatted bilinear weights + byte offsets into fp16 plane
#define PARAMS(KI, PB) do {                                                        \
        float2 dxy = *(const float2*)(goffp + 2 * (KI));                           \
        float py  = (float)(ph + (KI) / 3 - 1) + dxy.x;                            \
        float pxx = (float)(pw + (KI) % 3 - 1) + dxy.y;                            \
        float y0f = floorf(py), x0f = floorf(pxx);                                 \
        float ly = py - y0f, lx = pxx - x0f;                                       \
        int y0 = (int)y0f, x0 = (int)x0f, y1 = y0 + 1, x1 = x0 + 1;                \
        float w00 = (1.f - ly) * (1.f - lx), w01 = (1.f - ly) * lx;                \
        float w10 = ly * (1.f - lx), w11 = ly * lx;                                \
        bool vy0 = (unsigned)y0 < HH, vy1 = (unsigned)y1 < HH;                     \
        bool vx0 = (unsigned)x0 < WW, vx1 = (unsigned)x1 < WW;                     \
        w00 *= (float)(vy0 && vx0); w01 *= (float)(vy0 && vx1);                    \
        w10 *= (float)(vy1 && vx0); w11 *= (float)(vy1 && vx1);                    \
        int yc0 = min(max(y0, 0), HH - 1), yc1 = min(max(y1, 0), HH - 1);          \
        int xc0 = min(max(x0, 0), WW - 1), xc1 = min(max(x1, 0), WW - 1);          \
        uint4* p = (uint4*)(sP + (PB) * 1024) + tid * 2;                           \
        p[0] = make_uint4(splat_h2(w00), splat_h2(w01), splat_h2(w10), splat_h2(w11)); \
        p[1] = make_uint4((uint32_t)((yc0 * WW + xc0) * 128),                      \
                          (uint32_t)((yc0 * WW + xc1) * 128),                      \
                          (uint32_t)((yc1 * WW + xc0) * 128),                      \
                          (uint32_t)((yc1 * WW + xc1) * 128));                     \
    } while (0)

// half2 bilinear from fp16 corners (LDG.64 each)
#define BILIN(wvu, iv, OUT0, OUT1) do {                                            \
        uint2 a2 = *(const uint2*)(xh16 + iv.x + ck * 8);                          \
        uint2 b2 = *(const uint2*)(xh16 + iv.y + ck * 8);                          \
        uint2 c2 = *(const uint2*)(xh16 + iv.z + ck * 8);                          \
        uint2 d2 = *(const uint2*)(xh16 + iv.w + ck * 8);                          \
        __half2 s0 = __hmul2(u2h(a2.x), u2h(wvu.x));                               \
        s0 = __hfma2(u2h(b2.x), u2h(wvu.y), s0);                                   \
        s0 = __hfma2(u2h(c2.x), u2h(wvu.z), s0);                                   \
        s0 = __hfma2(u2h(d2.x), u2h(wvu.w), s0);                                   \
        __half2 s1 = __hmul2(u2h(a2.y), u2h(wvu.x));                               \
        s1 = __hfma2(u2h(b2.y), u2h(wvu.y), s1);                                   \
        s1 = __hfma2(u2h(c2.y), u2h(wvu.z), s1);                                   \
        s1 = __hfma2(u2h(d2.y), u2h(wvu.w), s1);                                   \
        OUT0 = h2u(s0); OUT1 = h2u(s1);                                            \
    } while (0)

#define GATHER0() do {                                                             \
        uint32_t dh = sb + swbase;                                                 \
        const uint4* sPp = (const uint4*)sP;                                       \
        _Pragma("unroll")                                                          \
        for (int ps = 0; ps < 8; ps++) {                                           \
            const uint4* pp = sPp + (ps * 16 + lpx) * 2;                           \
            uint4 wvu = pp[0], iv = pp[1];                                         \
            uint32_t o0, o1;                                                       \
            BILIN(wvu, iv, o0, o1);                                                \
            STS64(dh + ps * 2048, o0, o1);                                         \
        }                                                                          \
    } while (0)

#define WCOPYW(KI, BUF) do {                                                       \
        const char* srcw = (const char*)(g_wdc16 + (size_t)(KI) * 512);            \
        uint32_t dstw = sb + MAIN_SW + (BUF) * 8192;                               \
        for (int i = tid - 128; i < 512; i += 128) CPA16(dstw + i * 16, srcw + i * 16); \
    } while (0)

        if (tid < 128) PARAMS(0, 0);
        else           WCOPYW(0, 0);
        __syncthreads();
        GATHER0();
        if (tid < 128) PARAMS(1, 1);
        CPWAITALL();
        __syncthreads();

#pragma unroll 1
        for (int k = 0; k < KK; k++) {
            int buf = k & 1;
            if (tid < 128) {
                if (k < KK - 2) PARAMS(k + 2, buf);
            } else {
                if (k < KK - 1) WCOPYW(k + 1, buf ^ 1);
            }
            uint32_t abF = sb + buf * 16384;
            uint32_t wbF = sb + MAIN_SW + buf * 8192;
            uint32_t dh = sb + (buf ^ 1) * 16384 + swbase;
            const uint4* sPp = (const uint4*)(sP + ((k + 1) & 1) * 1024);
            bool dog = (k < KK - 1);

            uint32_t bF[2][4];
#pragma unroll
            for (int sub = 0; sub < 8; sub++) {
                const int kt = sub >> 1, mt = sub & 1;
                uint4 wvu, iv;
                if (dog) {
                    const uint4* pp = sPp + (sub * 16 + lpx) * 2;
                    wvu = pp[0]; iv = pp[1];
                }
                uint32_t colA = ((uint32_t)(kt * 32) + segA) ^ lmask;
                uint32_t aF[4];
                ldm4(aF, abF + arow[mt] + colA);
                if (mt == 0) {
                    uint32_t colB = ((uint32_t)(kt * 32) + segB) ^ lmask;
                    ldm4(bF[0], wbF + brow[0] + colB);
                    ldm4(bF[1], wbF + brow[1] + colB);
                }
#pragma unroll
                for (int nt = 0; nt < 4; nt++) {
                    int ntp = nt >> 1, hi2 = (nt & 1) * 2;
                    mma_f16(acc[mt][nt], aF, bF[ntp][hi2], bF[ntp][hi2 + 1]);
                }
                if (dog) {
                    uint32_t o0, o1;
                    BILIN(wvu, iv, o0, o1);
                    STS64(dh + sub * 2048, o0, o1);
                }
            }
            CPWAITALL();
            __syncthreads();
        }

        // epilogue B: transpose via smem, coalesced NCHW float4 stores
        float* oT = (float*)smem;   // [64][132]
#pragma unroll
        for (int mt = 0; mt < 2; mt++)
#pragma unroll
            for (int nt = 0; nt < 4; nt++) {
                int o = n0 + nt * 8 + (lane & 3) * 2;
                int p = m0 + mt * 16 + (lane >> 2);
                oT[o * 132 + p]           = acc[mt][nt][0];
                oT[(o + 1) * 132 + p]     = acc[mt][nt][1];
                oT[o * 132 + p + 8]       = acc[mt][nt][2];
                oT[(o + 1) * 132 + p + 8] = acc[mt][nt][3];
            }
        __syncthreads();
        {
            size_t obase = (size_t)b * OO * HWIMG + ip0;
            for (int i = tid; i < OO * (MT / 4); i += 256) {
                int o = i >> 5, p4 = i & 31;
                float4 v = *(const float4*)(oT + o * 132 + p4 * 4);
                *(float4*)(out + obase + (size_t)o * HWIMG + p4 * 4) = v;
            }
        }
#undef PARAMS
#undef BILIN
#undef GATHER0
#undef WCOPYW
    }
}

// ---------------- launch ----------------
extern "C" void kernel_launch(void* const* d_in, const int* in_sizes, int n_in,
                              void* d_out, int out_size) {
    const float* x     = (const float*)d_in[0];
    const float* w_off = (const float*)d_in[1];
    const float* b_off = (const float*)d_in[2];
    const float* w_dc  = (const float*)d_in[3];
    const float* b_dc  = (const float*)d_in[4];
    float* out = (float*)d_out;

    cudaFuncSetAttribute(k_fused, cudaFuncAttributeMaxDynamicSharedMemorySize, MAIN_SMEM);

    k_prep<<<BB * HH + (OO * CC * KK + 255) / 256, 256>>>(x, w_off, w_dc);
    k_fused<<<NTIL, 256, MAIN_SMEM>>>(b_off, b_dc, out);
}